// round 12
// baseline (speedup 1.0000x reference)
#include <cuda_runtime.h>
#include <cuda_bf16.h>
#include <math.h>
#include <stdint.h>

// Problem constants
#define DMODEL 768
#define FFND   3072
#define SEQ    2048
#define BATCH  2
#define NTOK   4096
#define NHEAD  12
#define HDIM   64

typedef __nv_bfloat16 bf16;

// ---------------------------------------------------------------------------
// Scratch (__device__ globals; no allocations allowed)
// ---------------------------------------------------------------------------
__device__ float g_p [NTOK * DMODEL];
__device__ float g_p2[NTOK * DMODEL];
__device__ float g_p3[NTOK * DMODEL];
__device__ float g_x1[NTOK * DMODEL];
__device__ float g_f [NTOK * DMODEL];
__device__ float g_f2[NTOK * DMODEL];
__device__ float g_f3[NTOK * DMODEL];
__device__ float g_zero[DMODEL];          // zero-initialized, never written

__device__ bf16 g_xh [NTOK * DMODEL], g_xl [NTOK * DMODEL];
__device__ bf16 g_qh [NTOK * DMODEL], g_ql [NTOK * DMODEL];
__device__ bf16 g_kh [NTOK * DMODEL], g_kl [NTOK * DMODEL];
__device__ bf16 g_vh [NTOK * DMODEL], g_vl [NTOK * DMODEL];
__device__ bf16 g_ah [NTOK * DMODEL], g_al [NTOK * DMODEL];
__device__ bf16 g_x1h[NTOK * DMODEL], g_x1l[NTOK * DMODEL];
__device__ bf16 g_hh [NTOK * FFND],   g_hl [NTOK * FFND];
__device__ bf16 g_Wqh[DMODEL*DMODEL], g_Wql[DMODEL*DMODEL];
__device__ bf16 g_Wkh[DMODEL*DMODEL], g_Wkl[DMODEL*DMODEL];
__device__ bf16 g_Wvh[DMODEL*DMODEL], g_Wvl[DMODEL*DMODEL];
__device__ bf16 g_Woh[DMODEL*DMODEL], g_Wol[DMODEL*DMODEL];
__device__ bf16 g_W1h[FFND*DMODEL],   g_W1l[FFND*DMODEL];
__device__ bf16 g_W2h[DMODEL*FFND],   g_W2l[DMODEL*FFND];

// ---------------------------------------------------------------------------
// PTX helpers (sm_103 base target safe)
// ---------------------------------------------------------------------------
__device__ __forceinline__ uint32_t smem_u32(const void* p) {
    uint32_t a;
    asm("{ .reg .u64 t; cvta.to.shared.u64 t, %1; cvt.u32.u64 %0, t; }"
        : "=r"(a) : "l"(p));
    return a;
}

#define CP16(dst, src) \
    asm volatile("cp.async.cg.shared.global [%0], [%1], 16;" :: "r"(dst), "l"(src))
#define CP_COMMIT() asm volatile("cp.async.commit_group;" ::: "memory")
#define CP_WAIT0()  asm volatile("cp.async.wait_group 0;" ::: "memory")
#define CP_WAIT1()  asm volatile("cp.async.wait_group 1;" ::: "memory")
#define CP_WAIT2()  asm volatile("cp.async.wait_group 2;" ::: "memory")

__device__ __forceinline__ void ldsm4(uint32_t a, uint32_t& r0, uint32_t& r1,
                                      uint32_t& r2, uint32_t& r3) {
    asm volatile("ldmatrix.sync.aligned.m8n8.x4.shared.b16 {%0,%1,%2,%3}, [%4];"
                 : "=r"(r0), "=r"(r1), "=r"(r2), "=r"(r3) : "r"(a));
}
__device__ __forceinline__ void ldsm4t(uint32_t a, uint32_t& r0, uint32_t& r1,
                                       uint32_t& r2, uint32_t& r3) {
    asm volatile("ldmatrix.sync.aligned.m8n8.x4.trans.shared.b16 {%0,%1,%2,%3}, [%4];"
                 : "=r"(r0), "=r"(r1), "=r"(r2), "=r"(r3) : "r"(a));
}

__device__ __forceinline__ void mma16816(float* d, const uint32_t* a,
                                         uint32_t b0, uint32_t b1) {
    asm volatile("mma.sync.aligned.m16n8k16.row.col.f32.bf16.bf16.f32 "
                 "{%0,%1,%2,%3}, {%4,%5,%6,%7}, {%8,%9}, {%0,%1,%2,%3};"
                 : "+f"(d[0]), "+f"(d[1]), "+f"(d[2]), "+f"(d[3])
                 : "r"(a[0]), "r"(a[1]), "r"(a[2]), "r"(a[3]), "r"(b0), "r"(b1));
}

// fast exp2
__device__ __forceinline__ float fexp2(float x) {
    float y;
    asm("ex2.approx.f32 %0, %1;" : "=f"(y) : "f"(x));
    return y;
}

// split two floats -> packed bf16x2 (hi) and bf16x2 (lo), 1-instr packing
__device__ __forceinline__ void split2(float a, float b, uint32_t& hi, uint32_t& lo) {
    asm("cvt.rn.bf16x2.f32 %0, %1, %2;" : "=r"(hi) : "f"(b), "f"(a));
    float ha = __uint_as_float(hi << 16);
    float hb = __uint_as_float(hi & 0xffff0000u);
    asm("cvt.rn.bf16x2.f32 %0, %1, %2;" : "=r"(lo) : "f"(b - hb), "f"(a - ha));
}

// ---------------------------------------------------------------------------
// Merged split conversion, MLP=4: each thread loads 4 independent float4s.
// Block = 1024 float4 = 4096 elems.
// ---------------------------------------------------------------------------
#define CB_X   (NTOK*DMODEL/4096)           // 768
#define CB_W   (DMODEL*DMODEL/4096)         // 144
#define CB_F   (FFND*DMODEL/4096)           // 576
#define CB_TOTAL (CB_X + 4*CB_W + 2*CB_F)   // 2496

__global__ void __launch_bounds__(256) cvt_all_kernel(
    const float* __restrict__ x,
    const float* __restrict__ Wq, const float* __restrict__ Wk,
    const float* __restrict__ Wv, const float* __restrict__ Wo,
    const float* __restrict__ W1, const float* __restrict__ W2,
    bf16* __restrict__ xh,  bf16* __restrict__ xl,
    bf16* __restrict__ Wqh, bf16* __restrict__ Wql,
    bf16* __restrict__ Wkh, bf16* __restrict__ Wkl,
    bf16* __restrict__ Wvh, bf16* __restrict__ Wvl,
    bf16* __restrict__ Woh, bf16* __restrict__ Wol,
    bf16* __restrict__ W1h, bf16* __restrict__ W1l,
    bf16* __restrict__ W2h, bf16* __restrict__ W2l)
{
    int bi = blockIdx.x;
    const float* in; bf16 *hi, *lo; int base;
    if      (bi < CB_X)            { in = x;  hi = xh;  lo = xl;  base = 0; }
    else if (bi < CB_X + CB_W)     { in = Wq; hi = Wqh; lo = Wql; base = CB_X; }
    else if (bi < CB_X + 2*CB_W)   { in = Wk; hi = Wkh; lo = Wkl; base = CB_X + CB_W; }
    else if (bi < CB_X + 3*CB_W)   { in = Wv; hi = Wvh; lo = Wvl; base = CB_X + 2*CB_W; }
    else if (bi < CB_X + 4*CB_W)   { in = Wo; hi = Woh; lo = Wol; base = CB_X + 3*CB_W; }
    else if (bi < CB_X + 4*CB_W + CB_F)
                                   { in = W1; hi = W1h; lo = W1l; base = CB_X + 4*CB_W; }
    else                           { in = W2; hi = W2h; lo = W2l; base = CB_X + 4*CB_W + CB_F; }

    size_t e0 = (size_t)(bi - base) * 1024 + threadIdx.x;   // float4 index
    const float4* in4 = (const float4*)in;
    float4 v[4];
    #pragma unroll
    for (int j = 0; j < 4; j++) v[j] = in4[e0 + j * 256];   // 4 independent loads
    #pragma unroll
    for (int j = 0; j < 4; j++) {
        uint32_t h0, l0, h1, l1;
        split2(v[j].x, v[j].y, h0, l0);
        split2(v[j].z, v[j].w, h1, l1);
        size_t idx = (e0 + (size_t)j * 256) * 4;
        *(uint2*)(hi + idx) = make_uint2(h0, h1);
        *(uint2*)(lo + idx) = make_uint2(l0, l1);
    }
}

// ---------------------------------------------------------------------------
// Shared GEMM body (R8-measured structure): 128x128 tile, BK=32 (64B rows),
// 8 warps, 3-stage cp.async pipeline, 2 CTAs/SM. 3 MMA terms (hh, hl, lh).
// ---------------------------------------------------------------------------
#define GSTAGE 32768                       // 4 matrices x 8KB
#define GSMEM_BYTES (3*GSTAGE + 1024)      // 99328 -> 2 CTA/SM

template<int MODE>
__device__ __forceinline__ void gemm_body(
    const bf16* __restrict__ Ah, const bf16* __restrict__ Al,
    const bf16* __restrict__ Bh, const bf16* __restrict__ Bl,
    const float* __restrict__ bias,
    float* __restrict__ C, bf16* __restrict__ Ch, bf16* __restrict__ Cl,
    int N, int ldk, int kIter, int k0, float scale, int m0, int n0)
{
    extern __shared__ __align__(1024) char smem_raw[];
    uint32_t sb = smem_u32(smem_raw);
    sb = (sb + 1023) & ~1023u;

    const int tid  = threadIdx.x;
    const int lane = tid & 31, wid = tid >> 5;
    const int wm = wid & 3, wn = wid >> 2;

    float acc[2][8][4];
    #pragma unroll
    for (int i = 0; i < 2; i++)
        #pragma unroll
        for (int j = 0; j < 8; j++)
            #pragma unroll
            for (int q = 0; q < 4; q++) acc[i][j][q] = 0.f;

    const int lrow = tid >> 1;
    const int c2   = (tid & 1) * 2;
    const bf16* pAh = Ah + (size_t)(m0 + lrow) * ldk + k0;
    const bf16* pAl = Al + (size_t)(m0 + lrow) * ldk + k0;
    const bf16* pBh = Bh + (size_t)(n0 + lrow) * ldk + k0;
    const bf16* pBl = Bl + (size_t)(n0 + lrow) * ldk + k0;
    const uint32_t swr = (uint32_t)((lrow >> 1) & 3);

    auto load_stage = [&](int s, int kt) {
        uint32_t st = sb + s * GSTAGE + lrow * 64;
        size_t ko = (size_t)kt * 32;
        #pragma unroll
        for (int cc = 0; cc < 2; cc++) {
            int c = c2 + cc;
            uint32_t off = (uint32_t)((c ^ swr) << 4);
            CP16(st + off,         pAh + ko + c * 8);
            CP16(st + 8192 + off,  pAl + ko + c * 8);
            CP16(st + 16384 + off, pBh + ko + c * 8);
            CP16(st + 24576 + off, pBl + ko + c * 8);
        }
    };

    const int nk = kIter >> 5;       // k32 tiles, always >= 4 here
    load_stage(0, 0); CP_COMMIT();
    load_stage(1, 1); CP_COMMIT();

    const int l15 = lane & 15, lh = lane >> 4;
    const int arowbase = wm * 32 + l15;
    const int browbase = wn * 64 + l15;
    int slot = 0, nslot = 2;

    for (int kt = 0; kt < nk; kt++) {
        if (kt + 1 < nk) CP_WAIT1(); else CP_WAIT0();
        __syncthreads();
        if (kt + 2 < nk) {
            load_stage(nslot, kt + 2);
            CP_COMMIT();
        }
        uint32_t st = sb + slot * GSTAGE;

        #pragma unroll
        for (int ks = 0; ks < 2; ks++) {
            const int chunk = ks * 2 + lh;
            uint32_t ah[2][4], al[2][4];
            #pragma unroll
            for (int mi = 0; mi < 2; mi++) {
                int row = arowbase + mi * 16;
                uint32_t ad = st + row * 64 + ((chunk ^ ((row >> 1) & 3)) << 4);
                ldsm4(ad,        ah[mi][0], ah[mi][1], ah[mi][2], ah[mi][3]);
                ldsm4(ad + 8192, al[mi][0], al[mi][1], al[mi][2], al[mi][3]);
            }
            uint32_t bh[2][4], bl[2][4];
            {
                uint32_t bd = st + 16384 + browbase * 64
                            + ((chunk ^ ((browbase >> 1) & 3)) << 4);
                ldsm4(bd,        bh[0][0], bh[0][1], bh[0][2], bh[0][3]);
                ldsm4(bd + 8192, bl[0][0], bl[0][1], bl[0][2], bl[0][3]);
            }
            #pragma unroll
            for (int g = 0; g < 4; g++) {
                const int cur = g & 1;
                if (g < 3) {
                    int row = browbase + (g + 1) * 16;
                    uint32_t bd = st + 16384 + row * 64
                                + ((chunk ^ ((row >> 1) & 3)) << 4);
                    ldsm4(bd,        bh[cur^1][0], bh[cur^1][1],
                                     bh[cur^1][2], bh[cur^1][3]);
                    ldsm4(bd + 8192, bl[cur^1][0], bl[cur^1][1],
                                     bl[cur^1][2], bl[cur^1][3]);
                }
                #pragma unroll
                for (int mi = 0; mi < 2; mi++) {
                    mma16816(acc[mi][2*g],   ah[mi], bh[cur][0], bh[cur][2]);
                    mma16816(acc[mi][2*g],   ah[mi], bl[cur][0], bl[cur][2]);
                    mma16816(acc[mi][2*g],   al[mi], bh[cur][0], bh[cur][2]);
                    mma16816(acc[mi][2*g+1], ah[mi], bh[cur][1], bh[cur][3]);
                    mma16816(acc[mi][2*g+1], ah[mi], bl[cur][1], bl[cur][3]);
                    mma16816(acc[mi][2*g+1], al[mi], bh[cur][1], bh[cur][3]);
                }
            }
        }
        slot = (slot == 2) ? 0 : slot + 1;
        nslot = (nslot == 2) ? 0 : nslot + 1;
    }

    const int g4 = lane >> 2, t4 = lane & 3;
    #pragma unroll
    for (int mi = 0; mi < 2; mi++) {
        #pragma unroll
        for (int n = 0; n < 8; n++) {
            int row = m0 + wm * 32 + mi * 16 + g4;
            int col = n0 + wn * 64 + n * 8 + t4 * 2;
            float b0 = bias[col], b1 = bias[col + 1];
            float v00 = acc[mi][n][0] + b0, v01 = acc[mi][n][1] + b1;
            float v10 = acc[mi][n][2] + b0, v11 = acc[mi][n][3] + b1;
            if (MODE == 0) {
                *(float2*)(C + (size_t)row * N + col)       = make_float2(v00, v01);
                *(float2*)(C + (size_t)(row + 8) * N + col) = make_float2(v10, v11);
            } else {
                if (MODE == 1) {
                    v00 *= scale; v01 *= scale; v10 *= scale; v11 *= scale;
                } else {
                    v00 = 0.5f * v00 * (1.0f + erff(v00 * 0.70710678118654752f));
                    v01 = 0.5f * v01 * (1.0f + erff(v01 * 0.70710678118654752f));
                    v10 = 0.5f * v10 * (1.0f + erff(v10 * 0.70710678118654752f));
                    v11 = 0.5f * v11 * (1.0f + erff(v11 * 0.70710678118654752f));
                }
                uint32_t h0, l0, h1, l1;
                split2(v00, v01, h0, l0);
                split2(v10, v11, h1, l1);
                *(uint32_t*)(Ch + (size_t)row * N + col)       = h0;
                *(uint32_t*)(Ch + (size_t)(row + 8) * N + col) = h1;
                *(uint32_t*)(Cl + (size_t)row * N + col)       = l0;
                *(uint32_t*)(Cl + (size_t)(row + 8) * N + col) = l1;
            }
        }
    }
}

template<int MODE>
__global__ void __launch_bounds__(256, 2) gemm_mma(
    const bf16* __restrict__ Ah, const bf16* __restrict__ Al,
    const bf16* __restrict__ Bh, const bf16* __restrict__ Bl,
    const float* __restrict__ bias,
    float* __restrict__ C, bf16* __restrict__ Ch, bf16* __restrict__ Cl,
    int N, int K)
{
    gemm_body<MODE>(Ah, Al, Bh, Bl, bias, C, Ch, Cl, N, K, K, 0, 1.0f,
                    blockIdx.y * 128, blockIdx.x * 128);
}

// Split-K x3 (fp32 output): z=0 -> C0 (+bias), z=1 -> C1, z=2 -> C2.
__global__ void __launch_bounds__(256, 2) gemm_splitk(
    const bf16* __restrict__ Ah, const bf16* __restrict__ Al,
    const bf16* __restrict__ Bh, const bf16* __restrict__ Bl,
    const float* __restrict__ bias,
    float* __restrict__ C0, float* __restrict__ C1, float* __restrict__ C2,
    int N, int K)
{
    int z = blockIdx.z;
    int kh = K / 3;
    float* Cz = (z == 0) ? C0 : (z == 1) ? C1 : C2;
    gemm_body<0>(Ah, Al, Bh, Bl, z ? g_zero : bias, Cz,
                 nullptr, nullptr, N, K, kh, z * kh, 1.0f,
                 blockIdx.y * 128, blockIdx.x * 128);
}

// Combined QKV; Q pre-scaled by 0.125*log2(e) for exp2-domain softmax.
#define QSCALE (0.125f * 1.4426950408889634f)
__global__ void __launch_bounds__(256, 2) gemm_qkv(
    const bf16* __restrict__ Ah, const bf16* __restrict__ Al,
    const bf16* __restrict__ Wqh, const bf16* __restrict__ Wql,
    const bf16* __restrict__ Wkh, const bf16* __restrict__ Wkl,
    const bf16* __restrict__ Wvh, const bf16* __restrict__ Wvl,
    const float* __restrict__ bq, const float* __restrict__ bk,
    const float* __restrict__ bv,
    bf16* __restrict__ qh, bf16* __restrict__ ql,
    bf16* __restrict__ kh, bf16* __restrict__ kl,
    bf16* __restrict__ vh, bf16* __restrict__ vl)
{
    int z = blockIdx.z;
    const bf16* Bh = (z == 0) ? Wqh : (z == 1) ? Wkh : Wvh;
    const bf16* Bl = (z == 0) ? Wql : (z == 1) ? Wkl : Wvl;
    const float* bias = (z == 0) ? bq : (z == 1) ? bk : bv;
    bf16* Ch = (z == 0) ? qh : (z == 1) ? kh : vh;
    bf16* Cl = (z == 0) ? ql : (z == 1) ? kl : vl;
    float scale = (z == 0) ? QSCALE : 1.0f;
    gemm_body<1>(Ah, Al, Bh, Bl, bias, nullptr, Ch, Cl,
                 DMODEL, DMODEL, DMODEL, 0, scale,
                 blockIdx.y * 128, blockIdx.x * 128);
}

// ---------------------------------------------------------------------------
// Split-KV flash attention: Q-tile 64, key-tile 32, 8 warps = 4 q-groups x
// 2 key-parity groups (even/odd 32-key tiles). 6-buffer cp.async ring,
// single __syncthreads per 2-tile iteration, FlashDecode-style merge.
// smem: Qh 8K | Ql 8K | 6 x 16K KV ring  = 113 KB -> 2 CTA/SM.
// ---------------------------------------------------------------------------
#define ASMEM_BYTES (16384 + 6*16384 + 1024)   // 115712

__global__ void __launch_bounds__(256, 2) attn_mma(
    const bf16* __restrict__ Qh, const bf16* __restrict__ Ql,
    const bf16* __restrict__ Kh, const bf16* __restrict__ Kl,
    const bf16* __restrict__ Vh, const bf16* __restrict__ Vl,
    bf16* __restrict__ Oh, bf16* __restrict__ Ol)
{
    extern __shared__ __align__(1024) char smem_raw[];
    char* smem_al = (char*)((((uintptr_t)smem_raw) + 1023) & ~(uintptr_t)1023);
    uint32_t sb = smem_u32(smem_al);
    const uint32_t KVB = sb + 16384;

    const int tid  = threadIdx.x;
    const int lane = tid & 31, wid = tid >> 5;
    const int qg = wid & 3;          // q-group 0..3 (16 rows each)
    const int kg = wid >> 2;         // key-parity group: 0 = even tiles, 1 = odd
    const int l15 = lane & 15, lh = lane >> 4;
    const int g4 = lane >> 2, t4 = lane & 3;
    const int b = blockIdx.z, h = blockIdx.y;
    const int q0 = blockIdx.x * 64;
    const size_t hoff = (size_t)h * HDIM;

    // ---- Q tile load: 64 rows, hi at sb, lo at sb+8192 ----
    {
        int qrow = tid >> 2;          // 0..63
        int cb = (tid & 3) * 2;       // chunks {cb, cb+1} of 8
        size_t gidx = ((size_t)(b * SEQ + q0 + qrow)) * DMODEL + hoff;
        uint32_t st = sb + qrow * 128;
        #pragma unroll
        for (int c = cb; c < cb + 2; c++) {
            uint32_t ph = (uint32_t)((c ^ (qrow & 7)) << 4);
            CP16(st + ph,        Qh + gidx + c * 8);
            CP16(st + 8192 + ph, Ql + gidx + c * 8);
        }
    }
    CP_COMMIT();

    // ---- KV tile loader: one 32-key tile (16KB) into ring slot t%6 ----
    const int krow = tid >> 3;       // 0..31
    const int kc   = tid & 7;        // chunk 0..7
    auto load_kv = [&](int t) {
        uint32_t base = KVB + (t % 6) * 16384;
        size_t gidx = ((size_t)(b * SEQ + t * 32 + krow)) * DMODEL + hoff;
        uint32_t off = krow * 128 + ((kc ^ (krow & 7)) << 4);
        CP16(base + off,         Kh + gidx + kc * 8);
        CP16(base + 4096 + off,  Kl + gidx + kc * 8);
        CP16(base + 8192 + off,  Vh + gidx + kc * 8);
        CP16(base + 12288 + off, Vl + gidx + kc * 8);
    };
    load_kv(0); CP_COMMIT();
    load_kv(1); CP_COMMIT();
    load_kv(2); CP_COMMIT();
    load_kv(3); CP_COMMIT();

    float m0 = -1e30f, m1 = -1e30f, l0 = 0.f, l1 = 0.f;
    float o[8][4];
    #pragma unroll
    for (int j = 0; j < 8; j++)
        #pragma unroll
        for (int q = 0; q < 4; q++) o[j][q] = 0.f;

    const int NT = SEQ / 32;         // 64 key tiles
    const int arow = qg * 16 + l15;
    const uint32_t aph = sb + arow * 128;

    for (int j = 0; j < NT / 2; j++) {
        if (2*j + 2 < NT) CP_WAIT2(); else CP_WAIT0();
        __syncthreads();

        const int t = 2*j + kg;                     // this group's tile
        uint32_t stb = KVB + (t % 6) * 16384;

        // ---- S = Q_scaled @ K^T (3 terms), 16 q-rows x 32 keys ----
        float s[4][4];
        #pragma unroll
        for (int jj = 0; jj < 4; jj++)
            #pragma unroll
            for (int q = 0; q < 4; q++) s[jj][q] = 0.f;

        #pragma unroll
        for (int kc4 = 0; kc4 < 4; kc4++) {
            const int chunk = kc4 * 2 + lh;
            uint32_t aaddr = aph + ((chunk ^ (arow & 7)) << 4);
            uint32_t qh_[4], ql_[4];
            ldsm4(aaddr,        qh_[0], qh_[1], qh_[2], qh_[3]);
            ldsm4(aaddr + 8192, ql_[0], ql_[1], ql_[2], ql_[3]);
            #pragma unroll
            for (int g = 0; g < 2; g++) {
                int brow = g * 16 + l15;
                uint32_t baddr = stb + brow * 128 + ((chunk ^ (brow & 7)) << 4);
                uint32_t kh_[4], kl_[4];
                ldsm4(baddr,        kh_[0], kh_[1], kh_[2], kh_[3]);
                ldsm4(baddr + 4096, kl_[0], kl_[1], kl_[2], kl_[3]);
                mma16816(s[2*g],   qh_, kh_[0], kh_[2]);
                mma16816(s[2*g],   qh_, kl_[0], kl_[2]);
                mma16816(s[2*g],   ql_, kh_[0], kh_[2]);
                mma16816(s[2*g+1], qh_, kh_[1], kh_[3]);
                mma16816(s[2*g+1], qh_, kl_[1], kl_[3]);
                mma16816(s[2*g+1], ql_, kh_[1], kh_[3]);
            }
        }

        // ---- online softmax (exp2 domain) ----
        float mx0 = -1e30f, mx1 = -1e30f;
        #pragma unroll
        for (int jj = 0; jj < 4; jj++) {
            mx0 = fmaxf(mx0, fmaxf(s[jj][0], s[jj][1]));
            mx1 = fmaxf(mx1, fmaxf(s[jj][2], s[jj][3]));
        }
        mx0 = fmaxf(mx0, __shfl_xor_sync(0xffffffffu, mx0, 1));
        mx0 = fmaxf(mx0, __shfl_xor_sync(0xffffffffu, mx0, 2));
        mx1 = fmaxf(mx1, __shfl_xor_sync(0xffffffffu, mx1, 1));
        mx1 = fmaxf(mx1, __shfl_xor_sync(0xffffffffu, mx1, 2));

        float mn0 = fmaxf(m0, mx0), mn1 = fmaxf(m1, mx1);
        float a0 = fexp2(m0 - mn0), a1 = fexp2(m1 - mn1);
        m0 = mn0; m1 = mn1;

        float sum0 = 0.f, sum1 = 0.f;
        #pragma unroll
        for (int jj = 0; jj < 4; jj++) {
            s[jj][0] = fexp2(s[jj][0] - mn0);
            s[jj][1] = fexp2(s[jj][1] - mn0);
            s[jj][2] = fexp2(s[jj][2] - mn1);
            s[jj][3] = fexp2(s[jj][3] - mn1);
            sum0 += s[jj][0] + s[jj][1];
            sum1 += s[jj][2] + s[jj][3];
        }
        sum0 += __shfl_xor_sync(0xffffffffu, sum0, 1);
        sum0 += __shfl_xor_sync(0xffffffffu, sum0, 2);
        sum1 += __shfl_xor_sync(0xffffffffu, sum1, 1);
        sum1 += __shfl_xor_sync(0xffffffffu, sum1, 2);
        l0 = l0 * a0 + sum0;
        l1 = l1 * a1 + sum1;

        #pragma unroll
        for (int jj = 0; jj < 8; jj++) {
            o[jj][0] *= a0; o[jj][1] *= a0;
            o[jj][2] *= a1; o[jj][3] *= a1;
        }

        // ---- O += P @ V (3 terms), V via ldmatrix.trans ----
        #pragma unroll
        for (int kc2 = 0; kc2 < 2; kc2++) {
            uint32_t ph_[4], pl_[4];
            split2(s[2*kc2][0],   s[2*kc2][1],   ph_[0], pl_[0]);
            split2(s[2*kc2][2],   s[2*kc2][3],   ph_[1], pl_[1]);
            split2(s[2*kc2+1][0], s[2*kc2+1][1], ph_[2], pl_[2]);
            split2(s[2*kc2+1][2], s[2*kc2+1][3], ph_[3], pl_[3]);

            int vrow = kc2 * 16 + (lane & 7) + ((lane >> 3) & 1) * 8;
            #pragma unroll
            for (int nn = 0; nn < 4; nn++) {
                int colchunk = nn * 2 + (lane >> 4);
                uint32_t vaddr = stb + 8192 + vrow * 128
                               + ((colchunk ^ (vrow & 7)) << 4);
                uint32_t vh_[4], vl_[4];
                ldsm4t(vaddr,        vh_[0], vh_[1], vh_[2], vh_[3]);
                ldsm4t(vaddr + 4096, vl_[0], vl_[1], vl_[2], vl_[3]);
                mma16816(o[2*nn],   ph_, vh_[0], vh_[1]);
                mma16816(o[2*nn],   ph_, vl_[0], vl_[1]);
                mma16816(o[2*nn],   pl_, vh_[0], vh_[1]);
                mma16816(o[2*nn+1], ph_, vh_[2], vh_[3]);
                mma16816(o[2*nn+1], ph_, vl_[2], vl_[3]);
                mma16816(o[2*nn+1], pl_, vh_[2], vh_[3]);
            }
        }

        // ---- prefetch two tiles (targets freed one full iteration ago) ----
        if (2*j + 4 < NT) { load_kv(2*j + 4); CP_COMMIT(); }
        if (2*j + 5 < NT) { load_kv(2*j + 5); CP_COMMIT(); }
    }

    // ---- merge the two key-parity groups (FlashDecode-style) ----
    __syncthreads();
    float* Osm = (float*)(smem_al + 16384);   // 64 x 66 fp32
    float* mB  = Osm + 64 * 66;
    float* lB  = mB + 64;

    const int r0 = qg * 16 + g4, r1 = r0 + 8;
    if (kg == 1) {
        #pragma unroll
        for (int jj = 0; jj < 8; jj++) {
            int c = jj * 8 + t4 * 2;
            Osm[r0 * 66 + c]     = o[jj][0];
            Osm[r0 * 66 + c + 1] = o[jj][1];
            Osm[r1 * 66 + c]     = o[jj][2];
            Osm[r1 * 66 + c + 1] = o[jj][3];
        }
        if (t4 == 0) { mB[r0] = m0; lB[r0] = l0; mB[r1] = m1; lB[r1] = l1; }
    }
    __syncthreads();
    if (kg == 0) {
        float mb0 = mB[r0], lb0 = lB[r0], mb1 = mB[r1], lb1 = lB[r1];
        float M0 = fmaxf(m0, mb0), M1 = fmaxf(m1, mb1);
        float sA0 = fexp2(m0 - M0), sB0 = fexp2(mb0 - M0);
        float sA1 = fexp2(m1 - M1), sB1 = fexp2(mb1 - M1);
        float inv0 = 1.0f / (l0 * sA0 + lb0 * sB0);
        float inv1 = 1.0f / (l1 * sA1 + lb1 * sB1);
        int row0 = b * SEQ + q0 + r0;
        #pragma unroll
        for (int jj = 0; jj < 8; jj++) {
            int c = jj * 8 + t4 * 2;
            float v00 = (o[jj][0] * sA0 + Osm[r0*66 + c]     * sB0) * inv0;
            float v01 = (o[jj][1] * sA0 + Osm[r0*66 + c + 1] * sB0) * inv0;
            float v10 = (o[jj][2] * sA1 + Osm[r1*66 + c]     * sB1) * inv1;
            float v11 = (o[jj][3] * sA1 + Osm[r1*66 + c + 1] * sB1) * inv1;
            uint32_t h0, lo0, h1, lo1;
            split2(v00, v01, h0, lo0);
            split2(v10, v11, h1, lo1);
            int col = (int)hoff + c;
            *(uint32_t*)(Oh + (size_t)row0 * DMODEL + col)       = h0;
            *(uint32_t*)(Ol + (size_t)row0 * DMODEL + col)       = lo0;
            *(uint32_t*)(Oh + (size_t)(row0 + 8) * DMODEL + col) = h1;
            *(uint32_t*)(Ol + (size_t)(row0 + 8) * DMODEL + col) = lo1;
        }
    }
}

// ---------------------------------------------------------------------------
// Fused residual add + LayerNorm over (y0 + y1 + y2 + residual).
// ---------------------------------------------------------------------------
__global__ void __launch_bounds__(256) ln_res_kernel(
    const float* __restrict__ y0, const float* __restrict__ y1,
    const float* __restrict__ y2, const float* __restrict__ r,
    const float* __restrict__ g, const float* __restrict__ b,
    float* __restrict__ o, bf16* __restrict__ oh, bf16* __restrict__ ol)
{
    const int row = blockIdx.x;
    const int tid = threadIdx.x;
    const float* y0p = y0 + (size_t)row * DMODEL;
    const float* y1p = y1 + (size_t)row * DMODEL;
    const float* y2p = y2 + (size_t)row * DMODEL;
    const float* rp  = r  + (size_t)row * DMODEL;

    float v[3];
    float s = 0.f, ss = 0.f;
    #pragma unroll
    for (int j = 0; j < 3; j++) {
        int c = tid + j * 256;
        float a = y0p[c] + y1p[c] + y2p[c] + rp[c];
        v[j] = a; s += a; ss += a * a;
    }
    #pragma unroll
    for (int off = 16; off; off >>= 1) {
        s  += __shfl_xor_sync(0xffffffffu, s, off);
        ss += __shfl_xor_sync(0xffffffffu, ss, off);
    }
    __shared__ float sred[16];
    if ((tid & 31) == 0) { sred[tid >> 5] = s; sred[8 + (tid >> 5)] = ss; }
    __syncthreads();
    if (tid == 0) {
        float S = 0.f, SS = 0.f;
        #pragma unroll
        for (int w = 0; w < 8; w++) { S += sred[w]; SS += sred[8 + w]; }
        sred[0] = S * (1.0f / DMODEL);
        sred[1] = SS * (1.0f / DMODEL);
    }
    __syncthreads();
    float mu  = sred[0];
    float var = sred[1] - mu * mu;
    float rstd = rsqrtf(var + 1e-5f);
    float* op = o + (size_t)row * DMODEL;
    #pragma unroll
    for (int j = 0; j < 3; j++) {
        int c = tid + j * 256;
        float val = (v[j] - mu) * rstd * g[c] + b[c];
        op[c] = val;
        if (oh) {
            bf16 hv = __float2bfloat16(val);
            oh[(size_t)row * DMODEL + c] = hv;
            ol[(size_t)row * DMODEL + c] =
                __float2bfloat16(val - __bfloat162float(hv));
        }
    }
}

// ---------------------------------------------------------------------------
extern "C" void kernel_launch(void* const* d_in, const int* in_sizes, int n_in,
                              void* d_out, int out_size)
{
    const float* x     = (const float*)d_in[0];
    const float* Wq    = (const float*)d_in[1];
    const float* bq    = (const float*)d_in[2];
    const float* Wk    = (const float*)d_in[3];
    const float* bk    = (const float*)d_in[4];
    const float* Wv    = (const float*)d_in[5];
    const float* bv    = (const float*)d_in[6];
    const float* Wo    = (const float*)d_in[7];
    const float* bo    = (const float*)d_in[8];
    const float* ln1g  = (const float*)d_in[9];
    const float* ln1b  = (const float*)d_in[10];
    const float* ln2g  = (const float*)d_in[11];
    const float* ln2b  = (const float*)d_in[12];
    const float* W1    = (const float*)d_in[13];
    const float* b1    = (const float*)d_in[14];
    const float* W2    = (const float*)d_in[15];
    const float* b2    = (const float*)d_in[16];
    float* out = (float*)d_out;

    float *p, *p2, *p3, *x1, *f, *f2, *f3;
    cudaGetSymbolAddress((void**)&p,  g_p);
    cudaGetSymbolAddress((void**)&p2, g_p2);
    cudaGetSymbolAddress((void**)&p3, g_p3);
    cudaGetSymbolAddress((void**)&x1, g_x1);
    cudaGetSymbolAddress((void**)&f,  g_f);
    cudaGetSymbolAddress((void**)&f2, g_f2);
    cudaGetSymbolAddress((void**)&f3, g_f3);

    bf16 *xh,*xl,*qh,*ql,*kh,*kl,*vh,*vl,*ah,*al,*x1h,*x1l,*hh,*hl;
    bf16 *Wqh,*Wql,*Wkh,*Wkl,*Wvh,*Wvl,*Woh,*Wol,*W1h,*W1l,*W2h,*W2l;
    cudaGetSymbolAddress((void**)&xh,  g_xh);  cudaGetSymbolAddress((void**)&xl,  g_xl);
    cudaGetSymbolAddress((void**)&qh,  g_qh);  cudaGetSymbolAddress((void**)&ql,  g_ql);
    cudaGetSymbolAddress((void**)&kh,  g_kh);  cudaGetSymbolAddress((void**)&kl,  g_kl);
    cudaGetSymbolAddress((void**)&vh,  g_vh);  cudaGetSymbolAddress((void**)&vl,  g_vl);
    cudaGetSymbolAddress((void**)&ah,  g_ah);  cudaGetSymbolAddress((void**)&al,  g_al);
    cudaGetSymbolAddress((void**)&x1h, g_x1h); cudaGetSymbolAddress((void**)&x1l, g_x1l);
    cudaGetSymbolAddress((void**)&hh,  g_hh);  cudaGetSymbolAddress((void**)&hl,  g_hl);
    cudaGetSymbolAddress((void**)&Wqh, g_Wqh); cudaGetSymbolAddress((void**)&Wql, g_Wql);
    cudaGetSymbolAddress((void**)&Wkh, g_Wkh); cudaGetSymbolAddress((void**)&Wkl, g_Wkl);
    cudaGetSymbolAddress((void**)&Wvh, g_Wvh); cudaGetSymbolAddress((void**)&Wvl, g_Wvl);
    cudaGetSymbolAddress((void**)&Woh, g_Woh); cudaGetSymbolAddress((void**)&Wol, g_Wol);
    cudaGetSymbolAddress((void**)&W1h, g_W1h); cudaGetSymbolAddress((void**)&W1l, g_W1l);
    cudaGetSymbolAddress((void**)&W2h, g_W2h); cudaGetSymbolAddress((void**)&W2l, g_W2l);

    cudaFuncSetAttribute(gemm_mma<2>,
                         cudaFuncAttributeMaxDynamicSharedMemorySize, GSMEM_BYTES);
    cudaFuncSetAttribute(gemm_splitk,
                         cudaFuncAttributeMaxDynamicSharedMemorySize, GSMEM_BYTES);
    cudaFuncSetAttribute(gemm_qkv,
                         cudaFuncAttributeMaxDynamicSharedMemorySize, GSMEM_BYTES);
    cudaFuncSetAttribute(attn_mma,
                         cudaFuncAttributeMaxDynamicSharedMemorySize, ASMEM_BYTES);

    dim3 blk(256);

    // Merged split conversion, MLP=4
    cvt_all_kernel<<<CB_TOTAL, blk>>>(x, Wq, Wk, Wv, Wo, W1, W2,
                                      xh, xl, Wqh, Wql, Wkh, Wkl, Wvh, Wvl,
                                      Woh, Wol, W1h, W1l, W2h, W2l);

    // QKV combined (bf16 split out; Q pre-scaled by 0.125*log2e)
    dim3 gqkv(DMODEL / 128, NTOK / 128, 3);
    gemm_qkv<<<gqkv, blk, GSMEM_BYTES>>>(xh, xl, Wqh, Wql, Wkh, Wkl, Wvh, Wvl,
                                         bq, bk, bv, qh, ql, kh, kl, vh, vl);

    // Attention: Q-tile 64, split-KV over warp groups
    dim3 ga(SEQ / 64, NHEAD, BATCH);
    attn_mma<<<ga, blk, ASMEM_BYTES>>>(qh, ql, kh, kl, vh, vl, ah, al);

    // Output projection (split-K x3) + residual LN1
    dim3 gS(DMODEL / 128, NTOK / 128, 3);
    gemm_splitk<<<gS, blk, GSMEM_BYTES>>>(ah, al, Woh, Wol, bo, p, p2, p3,
                                          DMODEL, DMODEL);
    ln_res_kernel<<<NTOK, blk>>>(p, p2, p3, x, ln1g, ln1b, x1, x1h, x1l);

    // FFN1 (GELU, bf16 split hidden)
    dim3 gF(FFND / 128, NTOK / 128);
    gemm_mma<2><<<gF, blk, GSMEM_BYTES>>>(x1h, x1l, W1h, W1l, b1,
                                          nullptr, hh, hl, FFND, DMODEL);
    // FFN2 (split-K x3) + residual LN2 -> out
    gemm_splitk<<<gS, blk, GSMEM_BYTES>>>(hh, hl, W2h, W2l, b2, f, f2, f3,
                                          DMODEL, FFND);
    ln_res_kernel<<<NTOK, blk>>>(f, f2, f3, x1, ln2g, ln2b, out, nullptr, nullptr);
}

// round 13
// speedup vs baseline: 1.0100x; 1.0100x over previous
#include <cuda_runtime.h>
#include <cuda_bf16.h>
#include <math.h>
#include <stdint.h>

// Problem constants
#define DMODEL 768
#define FFND   3072
#define SEQ    2048
#define BATCH  2
#define NTOK   4096
#define NHEAD  12
#define HDIM   64

typedef __nv_bfloat16 bf16;

// ---------------------------------------------------------------------------
// Scratch (__device__ globals; no allocations allowed)
// ---------------------------------------------------------------------------
__device__ float g_p [NTOK * DMODEL];
__device__ float g_p2[NTOK * DMODEL];
__device__ float g_p3[NTOK * DMODEL];
__device__ float g_x1[NTOK * DMODEL];
__device__ float g_f [NTOK * DMODEL];
__device__ float g_f2[NTOK * DMODEL];
__device__ float g_f3[NTOK * DMODEL];
__device__ float g_zero[DMODEL];          // zero-initialized, never written

__device__ bf16 g_xh [NTOK * DMODEL], g_xl [NTOK * DMODEL];
__device__ bf16 g_qh [NTOK * DMODEL], g_ql [NTOK * DMODEL];
__device__ bf16 g_kh [NTOK * DMODEL], g_kl [NTOK * DMODEL];
__device__ bf16 g_vh [NTOK * DMODEL], g_vl [NTOK * DMODEL];
__device__ bf16 g_ah [NTOK * DMODEL], g_al [NTOK * DMODEL];
__device__ bf16 g_x1h[NTOK * DMODEL], g_x1l[NTOK * DMODEL];
__device__ bf16 g_hh [NTOK * FFND],   g_hl [NTOK * FFND];
__device__ bf16 g_Wqh[DMODEL*DMODEL], g_Wql[DMODEL*DMODEL];
__device__ bf16 g_Wkh[DMODEL*DMODEL], g_Wkl[DMODEL*DMODEL];
__device__ bf16 g_Wvh[DMODEL*DMODEL], g_Wvl[DMODEL*DMODEL];
__device__ bf16 g_Woh[DMODEL*DMODEL], g_Wol[DMODEL*DMODEL];
__device__ bf16 g_W1h[FFND*DMODEL],   g_W1l[FFND*DMODEL];
__device__ bf16 g_W2h[DMODEL*FFND],   g_W2l[DMODEL*FFND];

// ---------------------------------------------------------------------------
// PTX helpers (sm_103 base target safe)
// ---------------------------------------------------------------------------
__device__ __forceinline__ uint32_t smem_u32(const void* p) {
    uint32_t a;
    asm("{ .reg .u64 t; cvta.to.shared.u64 t, %1; cvt.u32.u64 %0, t; }"
        : "=r"(a) : "l"(p));
    return a;
}

#define CP16(dst, src) \
    asm volatile("cp.async.cg.shared.global [%0], [%1], 16;" :: "r"(dst), "l"(src))
#define CP_COMMIT() asm volatile("cp.async.commit_group;" ::: "memory")
#define CP_WAIT0()  asm volatile("cp.async.wait_group 0;" ::: "memory")
#define CP_WAIT1()  asm volatile("cp.async.wait_group 1;" ::: "memory")

__device__ __forceinline__ void ldsm4(uint32_t a, uint32_t& r0, uint32_t& r1,
                                      uint32_t& r2, uint32_t& r3) {
    asm volatile("ldmatrix.sync.aligned.m8n8.x4.shared.b16 {%0,%1,%2,%3}, [%4];"
                 : "=r"(r0), "=r"(r1), "=r"(r2), "=r"(r3) : "r"(a));
}
__device__ __forceinline__ void ldsm4t(uint32_t a, uint32_t& r0, uint32_t& r1,
                                       uint32_t& r2, uint32_t& r3) {
    asm volatile("ldmatrix.sync.aligned.m8n8.x4.trans.shared.b16 {%0,%1,%2,%3}, [%4];"
                 : "=r"(r0), "=r"(r1), "=r"(r2), "=r"(r3) : "r"(a));
}

__device__ __forceinline__ void mma16816(float* d, const uint32_t* a,
                                         uint32_t b0, uint32_t b1) {
    asm volatile("mma.sync.aligned.m16n8k16.row.col.f32.bf16.bf16.f32 "
                 "{%0,%1,%2,%3}, {%4,%5,%6,%7}, {%8,%9}, {%0,%1,%2,%3};"
                 : "+f"(d[0]), "+f"(d[1]), "+f"(d[2]), "+f"(d[3])
                 : "r"(a[0]), "r"(a[1]), "r"(a[2]), "r"(a[3]), "r"(b0), "r"(b1));
}

// fast exp2
__device__ __forceinline__ float fexp2(float x) {
    float y;
    asm("ex2.approx.f32 %0, %1;" : "=f"(y) : "f"(x));
    return y;
}

// split two floats -> packed bf16x2 (hi) and bf16x2 (lo), 1-instr packing
__device__ __forceinline__ void split2(float a, float b, uint32_t& hi, uint32_t& lo) {
    asm("cvt.rn.bf16x2.f32 %0, %1, %2;" : "=r"(hi) : "f"(b), "f"(a));
    float ha = __uint_as_float(hi << 16);
    float hb = __uint_as_float(hi & 0xffff0000u);
    asm("cvt.rn.bf16x2.f32 %0, %1, %2;" : "=r"(lo) : "f"(b - hb), "f"(a - ha));
}

// ---------------------------------------------------------------------------
// Merged split conversion, MLP=4: each thread loads 4 independent float4s.
// Block = 1024 float4 = 4096 elems.
// ---------------------------------------------------------------------------
#define CB_X   (NTOK*DMODEL/4096)           // 768
#define CB_W   (DMODEL*DMODEL/4096)         // 144
#define CB_F   (FFND*DMODEL/4096)           // 576
#define CB_TOTAL (CB_X + 4*CB_W + 2*CB_F)   // 2496

__global__ void __launch_bounds__(256) cvt_all_kernel(
    const float* __restrict__ x,
    const float* __restrict__ Wq, const float* __restrict__ Wk,
    const float* __restrict__ Wv, const float* __restrict__ Wo,
    const float* __restrict__ W1, const float* __restrict__ W2,
    bf16* __restrict__ xh,  bf16* __restrict__ xl,
    bf16* __restrict__ Wqh, bf16* __restrict__ Wql,
    bf16* __restrict__ Wkh, bf16* __restrict__ Wkl,
    bf16* __restrict__ Wvh, bf16* __restrict__ Wvl,
    bf16* __restrict__ Woh, bf16* __restrict__ Wol,
    bf16* __restrict__ W1h, bf16* __restrict__ W1l,
    bf16* __restrict__ W2h, bf16* __restrict__ W2l)
{
    int bi = blockIdx.x;
    const float* in; bf16 *hi, *lo; int base;
    if      (bi < CB_X)            { in = x;  hi = xh;  lo = xl;  base = 0; }
    else if (bi < CB_X + CB_W)     { in = Wq; hi = Wqh; lo = Wql; base = CB_X; }
    else if (bi < CB_X + 2*CB_W)   { in = Wk; hi = Wkh; lo = Wkl; base = CB_X + CB_W; }
    else if (bi < CB_X + 3*CB_W)   { in = Wv; hi = Wvh; lo = Wvl; base = CB_X + 2*CB_W; }
    else if (bi < CB_X + 4*CB_W)   { in = Wo; hi = Woh; lo = Wol; base = CB_X + 3*CB_W; }
    else if (bi < CB_X + 4*CB_W + CB_F)
                                   { in = W1; hi = W1h; lo = W1l; base = CB_X + 4*CB_W; }
    else                           { in = W2; hi = W2h; lo = W2l; base = CB_X + 4*CB_W + CB_F; }

    size_t e0 = (size_t)(bi - base) * 1024 + threadIdx.x;   // float4 index
    const float4* in4 = (const float4*)in;
    float4 v[4];
    #pragma unroll
    for (int j = 0; j < 4; j++) v[j] = in4[e0 + j * 256];   // 4 independent loads
    #pragma unroll
    for (int j = 0; j < 4; j++) {
        uint32_t h0, l0, h1, l1;
        split2(v[j].x, v[j].y, h0, l0);
        split2(v[j].z, v[j].w, h1, l1);
        size_t idx = (e0 + (size_t)j * 256) * 4;
        *(uint2*)(hi + idx) = make_uint2(h0, h1);
        *(uint2*)(lo + idx) = make_uint2(l0, l1);
    }
}

// ---------------------------------------------------------------------------
// Shared GEMM body (R8-measured structure): 128x128 tile, BK=32 (64B rows),
// 8 warps, 3-stage cp.async pipeline, 2 CTAs/SM. 3 MMA terms (hh, hl, lh).
// A loaded up front per k16 step; B double-buffered within the k16 step.
// 64B-row swizzle: chunk ^= (row>>1)&3.
// MODE 0: fp32 C + bias.  MODE 1: bf16 split out, (acc+bias)*scale.
// MODE 2: GELU -> bf16 split out.
// ---------------------------------------------------------------------------
#define GSTAGE 32768                       // 4 matrices x 8KB
#define GSMEM_BYTES (3*GSTAGE + 1024)      // 99328 -> 2 CTA/SM

template<int MODE>
__device__ __forceinline__ void gemm_body(
    const bf16* __restrict__ Ah, const bf16* __restrict__ Al,
    const bf16* __restrict__ Bh, const bf16* __restrict__ Bl,
    const float* __restrict__ bias,
    float* __restrict__ C, bf16* __restrict__ Ch, bf16* __restrict__ Cl,
    int N, int ldk, int kIter, int k0, float scale, int m0, int n0)
{
    extern __shared__ __align__(1024) char smem_raw[];
    uint32_t sb = smem_u32(smem_raw);
    sb = (sb + 1023) & ~1023u;

    const int tid  = threadIdx.x;
    const int lane = tid & 31, wid = tid >> 5;
    const int wm = wid & 3, wn = wid >> 2;

    float acc[2][8][4];
    #pragma unroll
    for (int i = 0; i < 2; i++)
        #pragma unroll
        for (int j = 0; j < 8; j++)
            #pragma unroll
            for (int q = 0; q < 4; q++) acc[i][j][q] = 0.f;

    const int lrow = tid >> 1;
    const int c2   = (tid & 1) * 2;
    const bf16* pAh = Ah + (size_t)(m0 + lrow) * ldk + k0;
    const bf16* pAl = Al + (size_t)(m0 + lrow) * ldk + k0;
    const bf16* pBh = Bh + (size_t)(n0 + lrow) * ldk + k0;
    const bf16* pBl = Bl + (size_t)(n0 + lrow) * ldk + k0;
    const uint32_t swr = (uint32_t)((lrow >> 1) & 3);

    auto load_stage = [&](int s, int kt) {
        uint32_t st = sb + s * GSTAGE + lrow * 64;
        size_t ko = (size_t)kt * 32;
        #pragma unroll
        for (int cc = 0; cc < 2; cc++) {
            int c = c2 + cc;
            uint32_t off = (uint32_t)((c ^ swr) << 4);
            CP16(st + off,         pAh + ko + c * 8);
            CP16(st + 8192 + off,  pAl + ko + c * 8);
            CP16(st + 16384 + off, pBh + ko + c * 8);
            CP16(st + 24576 + off, pBl + ko + c * 8);
        }
    };

    const int nk = kIter >> 5;       // k32 tiles, always >= 4 here
    load_stage(0, 0); CP_COMMIT();
    load_stage(1, 1); CP_COMMIT();

    const int l15 = lane & 15, lh = lane >> 4;
    const int arowbase = wm * 32 + l15;
    const int browbase = wn * 64 + l15;
    int slot = 0, nslot = 2;

    for (int kt = 0; kt < nk; kt++) {
        if (kt + 1 < nk) CP_WAIT1(); else CP_WAIT0();
        __syncthreads();
        if (kt + 2 < nk) {
            load_stage(nslot, kt + 2);
            CP_COMMIT();
        }
        uint32_t st = sb + slot * GSTAGE;

        #pragma unroll
        for (int ks = 0; ks < 2; ks++) {
            const int chunk = ks * 2 + lh;
            uint32_t ah[2][4], al[2][4];
            #pragma unroll
            for (int mi = 0; mi < 2; mi++) {
                int row = arowbase + mi * 16;
                uint32_t ad = st + row * 64 + ((chunk ^ ((row >> 1) & 3)) << 4);
                ldsm4(ad,        ah[mi][0], ah[mi][1], ah[mi][2], ah[mi][3]);
                ldsm4(ad + 8192, al[mi][0], al[mi][1], al[mi][2], al[mi][3]);
            }
            uint32_t bh[2][4], bl[2][4];
            {
                uint32_t bd = st + 16384 + browbase * 64
                            + ((chunk ^ ((browbase >> 1) & 3)) << 4);
                ldsm4(bd,        bh[0][0], bh[0][1], bh[0][2], bh[0][3]);
                ldsm4(bd + 8192, bl[0][0], bl[0][1], bl[0][2], bl[0][3]);
            }
            #pragma unroll
            for (int g = 0; g < 4; g++) {
                const int cur = g & 1;
                if (g < 3) {
                    int row = browbase + (g + 1) * 16;
                    uint32_t bd = st + 16384 + row * 64
                                + ((chunk ^ ((row >> 1) & 3)) << 4);
                    ldsm4(bd,        bh[cur^1][0], bh[cur^1][1],
                                     bh[cur^1][2], bh[cur^1][3]);
                    ldsm4(bd + 8192, bl[cur^1][0], bl[cur^1][1],
                                     bl[cur^1][2], bl[cur^1][3]);
                }
                #pragma unroll
                for (int mi = 0; mi < 2; mi++) {
                    mma16816(acc[mi][2*g],   ah[mi], bh[cur][0], bh[cur][2]);
                    mma16816(acc[mi][2*g],   ah[mi], bl[cur][0], bl[cur][2]);
                    mma16816(acc[mi][2*g],   al[mi], bh[cur][0], bh[cur][2]);
                    mma16816(acc[mi][2*g+1], ah[mi], bh[cur][1], bh[cur][3]);
                    mma16816(acc[mi][2*g+1], ah[mi], bl[cur][1], bl[cur][3]);
                    mma16816(acc[mi][2*g+1], al[mi], bh[cur][1], bh[cur][3]);
                }
            }
        }
        slot = (slot == 2) ? 0 : slot + 1;
        nslot = (nslot == 2) ? 0 : nslot + 1;
    }

    const int g4 = lane >> 2, t4 = lane & 3;
    #pragma unroll
    for (int mi = 0; mi < 2; mi++) {
        #pragma unroll
        for (int n = 0; n < 8; n++) {
            int row = m0 + wm * 32 + mi * 16 + g4;
            int col = n0 + wn * 64 + n * 8 + t4 * 2;
            float b0 = bias[col], b1 = bias[col + 1];
            float v00 = acc[mi][n][0] + b0, v01 = acc[mi][n][1] + b1;
            float v10 = acc[mi][n][2] + b0, v11 = acc[mi][n][3] + b1;
            if (MODE == 0) {
                *(float2*)(C + (size_t)row * N + col)       = make_float2(v00, v01);
                *(float2*)(C + (size_t)(row + 8) * N + col) = make_float2(v10, v11);
            } else {
                if (MODE == 1) {
                    v00 *= scale; v01 *= scale; v10 *= scale; v11 *= scale;
                } else {
                    v00 = 0.5f * v00 * (1.0f + erff(v00 * 0.70710678118654752f));
                    v01 = 0.5f * v01 * (1.0f + erff(v01 * 0.70710678118654752f));
                    v10 = 0.5f * v10 * (1.0f + erff(v10 * 0.70710678118654752f));
                    v11 = 0.5f * v11 * (1.0f + erff(v11 * 0.70710678118654752f));
                }
                uint32_t h0, l0, h1, l1;
                split2(v00, v01, h0, l0);
                split2(v10, v11, h1, l1);
                *(uint32_t*)(Ch + (size_t)row * N + col)       = h0;
                *(uint32_t*)(Ch + (size_t)(row + 8) * N + col) = h1;
                *(uint32_t*)(Cl + (size_t)row * N + col)       = l0;
                *(uint32_t*)(Cl + (size_t)(row + 8) * N + col) = l1;
            }
        }
    }
}

template<int MODE>
__global__ void __launch_bounds__(256, 2) gemm_mma(
    const bf16* __restrict__ Ah, const bf16* __restrict__ Al,
    const bf16* __restrict__ Bh, const bf16* __restrict__ Bl,
    const float* __restrict__ bias,
    float* __restrict__ C, bf16* __restrict__ Ch, bf16* __restrict__ Cl,
    int N, int K)
{
    gemm_body<MODE>(Ah, Al, Bh, Bl, bias, C, Ch, Cl, N, K, K, 0, 1.0f,
                    blockIdx.y * 128, blockIdx.x * 128);
}

// Split-K x3 (fp32 output): z=0 -> C0 (+bias), z=1 -> C1, z=2 -> C2.
__global__ void __launch_bounds__(256, 2) gemm_splitk(
    const bf16* __restrict__ Ah, const bf16* __restrict__ Al,
    const bf16* __restrict__ Bh, const bf16* __restrict__ Bl,
    const float* __restrict__ bias,
    float* __restrict__ C0, float* __restrict__ C1, float* __restrict__ C2,
    int N, int K)
{
    int z = blockIdx.z;
    int kh = K / 3;
    float* Cz = (z == 0) ? C0 : (z == 1) ? C1 : C2;
    gemm_body<0>(Ah, Al, Bh, Bl, z ? g_zero : bias, Cz,
                 nullptr, nullptr, N, K, kh, z * kh, 1.0f,
                 blockIdx.y * 128, blockIdx.x * 128);
}

// Combined QKV; Q pre-scaled by 0.125*log2(e) for exp2-domain softmax.
#define QSCALE (0.125f * 1.4426950408889634f)
__global__ void __launch_bounds__(256, 2) gemm_qkv(
    const bf16* __restrict__ Ah, const bf16* __restrict__ Al,
    const bf16* __restrict__ Wqh, const bf16* __restrict__ Wql,
    const bf16* __restrict__ Wkh, const bf16* __restrict__ Wkl,
    const bf16* __restrict__ Wvh, const bf16* __restrict__ Wvl,
    const float* __restrict__ bq, const float* __restrict__ bk,
    const float* __restrict__ bv,
    bf16* __restrict__ qh, bf16* __restrict__ ql,
    bf16* __restrict__ kh, bf16* __restrict__ kl,
    bf16* __restrict__ vh, bf16* __restrict__ vl)
{
    int z = blockIdx.z;
    const bf16* Bh = (z == 0) ? Wqh : (z == 1) ? Wkh : Wvh;
    const bf16* Bl = (z == 0) ? Wql : (z == 1) ? Wkl : Wvl;
    const float* bias = (z == 0) ? bq : (z == 1) ? bk : bv;
    bf16* Ch = (z == 0) ? qh : (z == 1) ? kh : vh;
    bf16* Cl = (z == 0) ? ql : (z == 1) ? kl : vl;
    float scale = (z == 0) ? QSCALE : 1.0f;
    gemm_body<1>(Ah, Al, Bh, Bl, bias, nullptr, Ch, Cl,
                 DMODEL, DMODEL, DMODEL, 0, scale,
                 blockIdx.y * 128, blockIdx.x * 128);
}

// ---------------------------------------------------------------------------
// Flash attention (R11 config): Q-tile 128, key-tile 64, 8 warps x 16 q-rows,
// 2-stage KV cp.async, exp2-domain softmax. 99.3 KB smem -> 2 CTA/SM.
// ---------------------------------------------------------------------------
#define ASMEM_BYTES (32768 + 2*32768 + 1024)

__global__ void __launch_bounds__(256, 2) attn_mma(
    const bf16* __restrict__ Qh, const bf16* __restrict__ Ql,
    const bf16* __restrict__ Kh, const bf16* __restrict__ Kl,
    const bf16* __restrict__ Vh, const bf16* __restrict__ Vl,
    bf16* __restrict__ Oh, bf16* __restrict__ Ol)
{
    extern __shared__ __align__(1024) char smem_raw[];
    uint32_t sb = smem_u32(smem_raw);
    sb = (sb + 1023) & ~1023u;

    const int tid  = threadIdx.x;
    const int lane = tid & 31, wq = tid >> 5;
    const int l15 = lane & 15, lh = lane >> 4;
    const int g4 = lane >> 2, t4 = lane & 3;
    const int b = blockIdx.z, h = blockIdx.y;
    const int q0 = blockIdx.x * 128;
    const size_t hoff = (size_t)h * HDIM;

    {
        int qrow = tid >> 1;
        int cb = (tid & 1) * 4;
        size_t gidx = ((size_t)(b * SEQ + q0 + qrow)) * DMODEL + hoff;
        uint32_t st = sb + qrow * 128;
        #pragma unroll
        for (int c = 0; c < 4; c++) {
            uint32_t ph = (uint32_t)(((cb + c) ^ (qrow & 7)) << 4);
            CP16(st + ph,         Qh + gidx + (cb + c) * 8);
            CP16(st + 16384 + ph, Ql + gidx + (cb + c) * 8);
        }
    }
    CP_COMMIT();

    const int krow = tid >> 2;
    const int kc0  = (tid & 3) * 2;
    auto load_kv = [&](int s, int kt) {
        uint32_t base = sb + 32768 + s * 32768;
        size_t gidx = ((size_t)(b * SEQ + kt * 64 + krow)) * DMODEL + hoff;
        #pragma unroll
        for (int cc = 0; cc < 2; cc++) {
            int c = kc0 + cc;
            uint32_t off = krow * 128 + ((c ^ (krow & 7)) << 4);
            CP16(base + off,         Kh + gidx + c * 8);
            CP16(base + 8192 + off,  Kl + gidx + c * 8);
            CP16(base + 16384 + off, Vh + gidx + c * 8);
            CP16(base + 24576 + off, Vl + gidx + c * 8);
        }
    };
    load_kv(0, 0);
    CP_COMMIT();

    float m0 = -1e30f, m1 = -1e30f, l0 = 0.f, l1 = 0.f;
    float o[8][4];
    #pragma unroll
    for (int j = 0; j < 8; j++)
        #pragma unroll
        for (int q = 0; q < 4; q++) o[j][q] = 0.f;

    const int NT = SEQ / 64;
    for (int kt = 0; kt < NT; kt++) {
        CP_WAIT0();
        __syncthreads();
        if (kt + 1 < NT) {
            load_kv((kt + 1) & 1, kt + 1);
            CP_COMMIT();
        }

        uint32_t stb = sb + 32768 + (kt & 1) * 32768;

        float s[8][4];
        #pragma unroll
        for (int j = 0; j < 8; j++)
            #pragma unroll
            for (int q = 0; q < 4; q++) s[j][q] = 0.f;

        #pragma unroll
        for (int kc = 0; kc < 4; kc++) {
            const int chunk = kc * 2 + lh;
            int arow = wq * 16 + l15;
            uint32_t aaddr = sb + arow * 128 + ((chunk ^ (arow & 7)) << 4);
            uint32_t qh_[4], ql_[4];
            ldsm4(aaddr,         qh_[0], qh_[1], qh_[2], qh_[3]);
            ldsm4(aaddr + 16384, ql_[0], ql_[1], ql_[2], ql_[3]);
            #pragma unroll
            for (int g = 0; g < 4; g++) {
                int brow = g * 16 + l15;
                uint32_t baddr = stb + brow * 128 + ((chunk ^ (brow & 7)) << 4);
                uint32_t kh_[4], kl_[4];
                ldsm4(baddr,        kh_[0], kh_[1], kh_[2], kh_[3]);
                ldsm4(baddr + 8192, kl_[0], kl_[1], kl_[2], kl_[3]);
                mma16816(s[2*g],   qh_, kh_[0], kh_[2]);
                mma16816(s[2*g],   qh_, kl_[0], kl_[2]);
                mma16816(s[2*g],   ql_, kh_[0], kh_[2]);
                mma16816(s[2*g+1], qh_, kh_[1], kh_[3]);
                mma16816(s[2*g+1], qh_, kl_[1], kl_[3]);
                mma16816(s[2*g+1], ql_, kh_[1], kh_[3]);
            }
        }

        float mx0 = -1e30f, mx1 = -1e30f;
        #pragma unroll
        for (int j = 0; j < 8; j++) {
            mx0 = fmaxf(mx0, fmaxf(s[j][0], s[j][1]));
            mx1 = fmaxf(mx1, fmaxf(s[j][2], s[j][3]));
        }
        mx0 = fmaxf(mx0, __shfl_xor_sync(0xffffffffu, mx0, 1));
        mx0 = fmaxf(mx0, __shfl_xor_sync(0xffffffffu, mx0, 2));
        mx1 = fmaxf(mx1, __shfl_xor_sync(0xffffffffu, mx1, 1));
        mx1 = fmaxf(mx1, __shfl_xor_sync(0xffffffffu, mx1, 2));

        float mn0 = fmaxf(m0, mx0), mn1 = fmaxf(m1, mx1);
        float a0 = fexp2(m0 - mn0), a1 = fexp2(m1 - mn1);
        m0 = mn0; m1 = mn1;

        float sum0 = 0.f, sum1 = 0.f;
        #pragma unroll
        for (int j = 0; j < 8; j++) {
            s[j][0] = fexp2(s[j][0] - mn0);
            s[j][1] = fexp2(s[j][1] - mn0);
            s[j][2] = fexp2(s[j][2] - mn1);
            s[j][3] = fexp2(s[j][3] - mn1);
            sum0 += s[j][0] + s[j][1];
            sum1 += s[j][2] + s[j][3];
        }
        sum0 += __shfl_xor_sync(0xffffffffu, sum0, 1);
        sum0 += __shfl_xor_sync(0xffffffffu, sum0, 2);
        sum1 += __shfl_xor_sync(0xffffffffu, sum1, 1);
        sum1 += __shfl_xor_sync(0xffffffffu, sum1, 2);
        l0 = l0 * a0 + sum0;
        l1 = l1 * a1 + sum1;

        #pragma unroll
        for (int j = 0; j < 8; j++) {
            o[j][0] *= a0; o[j][1] *= a0;
            o[j][2] *= a1; o[j][3] *= a1;
        }

        #pragma unroll
        for (int kc = 0; kc < 4; kc++) {
            uint32_t ph_[4], pl_[4];
            split2(s[2*kc][0],   s[2*kc][1],   ph_[0], pl_[0]);
            split2(s[2*kc][2],   s[2*kc][3],   ph_[1], pl_[1]);
            split2(s[2*kc+1][0], s[2*kc+1][1], ph_[2], pl_[2]);
            split2(s[2*kc+1][2], s[2*kc+1][3], ph_[3], pl_[3]);

            int vrow = kc * 16 + (lane & 7) + ((lane >> 3) & 1) * 8;
            #pragma unroll
            for (int nn = 0; nn < 4; nn++) {
                int colchunk = nn * 2 + (lane >> 4);
                uint32_t vaddr = stb + 16384 + vrow * 128
                               + ((colchunk ^ (vrow & 7)) << 4);
                uint32_t vh_[4], vl_[4];
                ldsm4t(vaddr,        vh_[0], vh_[1], vh_[2], vh_[3]);
                ldsm4t(vaddr + 8192, vl_[0], vl_[1], vl_[2], vl_[3]);
                mma16816(o[2*nn],   ph_, vh_[0], vh_[1]);
                mma16816(o[2*nn],   ph_, vl_[0], vl_[1]);
                mma16816(o[2*nn],   pl_, vh_[0], vh_[1]);
                mma16816(o[2*nn+1], ph_, vh_[2], vh_[3]);
                mma16816(o[2*nn+1], ph_, vl_[2], vl_[3]);
                mma16816(o[2*nn+1], pl_, vh_[2], vh_[3]);
            }
        }
    }

    float i0 = 1.0f / l0, i1 = 1.0f / l1;
    int row0 = b * SEQ + q0 + wq * 16 + g4;
    #pragma unroll
    for (int j = 0; j < 8; j++) {
        int col = (int)hoff + j * 8 + t4 * 2;
        uint32_t h0, lo0, h1, lo1;
        split2(o[j][0] * i0, o[j][1] * i0, h0, lo0);
        split2(o[j][2] * i1, o[j][3] * i1, h1, lo1);
        *(uint32_t*)(Oh + (size_t)row0 * DMODEL + col)       = h0;
        *(uint32_t*)(Ol + (size_t)row0 * DMODEL + col)       = lo0;
        *(uint32_t*)(Oh + (size_t)(row0 + 8) * DMODEL + col) = h1;
        *(uint32_t*)(Ol + (size_t)(row0 + 8) * DMODEL + col) = lo1;
    }
}

// ---------------------------------------------------------------------------
// Fused residual add + LayerNorm over (y0 + y1 + y2 + residual).
// ---------------------------------------------------------------------------
__global__ void __launch_bounds__(256) ln_res_kernel(
    const float* __restrict__ y0, const float* __restrict__ y1,
    const float* __restrict__ y2, const float* __restrict__ r,
    const float* __restrict__ g, const float* __restrict__ b,
    float* __restrict__ o, bf16* __restrict__ oh, bf16* __restrict__ ol)
{
    const int row = blockIdx.x;
    const int tid = threadIdx.x;
    const float* y0p = y0 + (size_t)row * DMODEL;
    const float* y1p = y1 + (size_t)row * DMODEL;
    const float* y2p = y2 + (size_t)row * DMODEL;
    const float* rp  = r  + (size_t)row * DMODEL;

    float v[3];
    float s = 0.f, ss = 0.f;
    #pragma unroll
    for (int j = 0; j < 3; j++) {
        int c = tid + j * 256;
        float a = y0p[c] + y1p[c] + y2p[c] + rp[c];
        v[j] = a; s += a; ss += a * a;
    }
    #pragma unroll
    for (int off = 16; off; off >>= 1) {
        s  += __shfl_xor_sync(0xffffffffu, s, off);
        ss += __shfl_xor_sync(0xffffffffu, ss, off);
    }
    __shared__ float sred[16];
    if ((tid & 31) == 0) { sred[tid >> 5] = s; sred[8 + (tid >> 5)] = ss; }
    __syncthreads();
    if (tid == 0) {
        float S = 0.f, SS = 0.f;
        #pragma unroll
        for (int w = 0; w < 8; w++) { S += sred[w]; SS += sred[8 + w]; }
        sred[0] = S * (1.0f / DMODEL);
        sred[1] = SS * (1.0f / DMODEL);
    }
    __syncthreads();
    float mu  = sred[0];
    float var = sred[1] - mu * mu;
    float rstd = rsqrtf(var + 1e-5f);
    float* op = o + (size_t)row * DMODEL;
    #pragma unroll
    for (int j = 0; j < 3; j++) {
        int c = tid + j * 256;
        float val = (v[j] - mu) * rstd * g[c] + b[c];
        op[c] = val;
        if (oh) {
            bf16 hv = __float2bfloat16(val);
            oh[(size_t)row * DMODEL + c] = hv;
            ol[(size_t)row * DMODEL + c] =
                __float2bfloat16(val - __bfloat162float(hv));
        }
    }
}

// ---------------------------------------------------------------------------
extern "C" void kernel_launch(void* const* d_in, const int* in_sizes, int n_in,
                              void* d_out, int out_size)
{
    const float* x     = (const float*)d_in[0];
    const float* Wq    = (const float*)d_in[1];
    const float* bq    = (const float*)d_in[2];
    const float* Wk    = (const float*)d_in[3];
    const float* bk    = (const float*)d_in[4];
    const float* Wv    = (const float*)d_in[5];
    const float* bv    = (const float*)d_in[6];
    const float* Wo    = (const float*)d_in[7];
    const float* bo    = (const float*)d_in[8];
    const float* ln1g  = (const float*)d_in[9];
    const float* ln1b  = (const float*)d_in[10];
    const float* ln2g  = (const float*)d_in[11];
    const float* ln2b  = (const float*)d_in[12];
    const float* W1    = (const float*)d_in[13];
    const float* b1    = (const float*)d_in[14];
    const float* W2    = (const float*)d_in[15];
    const float* b2    = (const float*)d_in[16];
    float* out = (float*)d_out;

    float *p, *p2, *p3, *x1, *f, *f2, *f3;
    cudaGetSymbolAddress((void**)&p,  g_p);
    cudaGetSymbolAddress((void**)&p2, g_p2);
    cudaGetSymbolAddress((void**)&p3, g_p3);
    cudaGetSymbolAddress((void**)&x1, g_x1);
    cudaGetSymbolAddress((void**)&f,  g_f);
    cudaGetSymbolAddress((void**)&f2, g_f2);
    cudaGetSymbolAddress((void**)&f3, g_f3);

    bf16 *xh,*xl,*qh,*ql,*kh,*kl,*vh,*vl,*ah,*al,*x1h,*x1l,*hh,*hl;
    bf16 *Wqh,*Wql,*Wkh,*Wkl,*Wvh,*Wvl,*Woh,*Wol,*W1h,*W1l,*W2h,*W2l;
    cudaGetSymbolAddress((void**)&xh,  g_xh);  cudaGetSymbolAddress((void**)&xl,  g_xl);
    cudaGetSymbolAddress((void**)&qh,  g_qh);  cudaGetSymbolAddress((void**)&ql,  g_ql);
    cudaGetSymbolAddress((void**)&kh,  g_kh);  cudaGetSymbolAddress((void**)&kl,  g_kl);
    cudaGetSymbolAddress((void**)&vh,  g_vh);  cudaGetSymbolAddress((void**)&vl,  g_vl);
    cudaGetSymbolAddress((void**)&ah,  g_ah);  cudaGetSymbolAddress((void**)&al,  g_al);
    cudaGetSymbolAddress((void**)&x1h, g_x1h); cudaGetSymbolAddress((void**)&x1l, g_x1l);
    cudaGetSymbolAddress((void**)&hh,  g_hh);  cudaGetSymbolAddress((void**)&hl,  g_hl);
    cudaGetSymbolAddress((void**)&Wqh, g_Wqh); cudaGetSymbolAddress((void**)&Wql, g_Wql);
    cudaGetSymbolAddress((void**)&Wkh, g_Wkh); cudaGetSymbolAddress((void**)&Wkl, g_Wkl);
    cudaGetSymbolAddress((void**)&Wvh, g_Wvh); cudaGetSymbolAddress((void**)&Wvl, g_Wvl);
    cudaGetSymbolAddress((void**)&Woh, g_Woh); cudaGetSymbolAddress((void**)&Wol, g_Wol);
    cudaGetSymbolAddress((void**)&W1h, g_W1h); cudaGetSymbolAddress((void**)&W1l, g_W1l);
    cudaGetSymbolAddress((void**)&W2h, g_W2h); cudaGetSymbolAddress((void**)&W2l, g_W2l);

    cudaFuncSetAttribute(gemm_mma<2>,
                         cudaFuncAttributeMaxDynamicSharedMemorySize, GSMEM_BYTES);
    cudaFuncSetAttribute(gemm_splitk,
                         cudaFuncAttributeMaxDynamicSharedMemorySize, GSMEM_BYTES);
    cudaFuncSetAttribute(gemm_qkv,
                         cudaFuncAttributeMaxDynamicSharedMemorySize, GSMEM_BYTES);
    cudaFuncSetAttribute(attn_mma,
                         cudaFuncAttributeMaxDynamicSharedMemorySize, ASMEM_BYTES);

    dim3 blk(256);

    // Merged split conversion, MLP=4
    cvt_all_kernel<<<CB_TOTAL, blk>>>(x, Wq, Wk, Wv, Wo, W1, W2,
                                      xh, xl, Wqh, Wql, Wkh, Wkl, Wvh, Wvl,
                                      Woh, Wol, W1h, W1l, W2h, W2l);

    // QKV combined (bf16 split out; Q pre-scaled by 0.125*log2e)
    dim3 gqkv(DMODEL / 128, NTOK / 128, 3);
    gemm_qkv<<<gqkv, blk, GSMEM_BYTES>>>(xh, xl, Wqh, Wql, Wkh, Wkl, Wvh, Wvl,
                                         bq, bk, bv, qh, ql, kh, kl, vh, vl);

    // Attention (exp2-domain flash attention, Q-tile 128)
    dim3 ga(SEQ / 128, NHEAD, BATCH);
    attn_mma<<<ga, blk, ASMEM_BYTES>>>(qh, ql, kh, kl, vh, vl, ah, al);

    // Output projection (split-K x3) + residual LN1
    dim3 gS(DMODEL / 128, NTOK / 128, 3);
    gemm_splitk<<<gS, blk, GSMEM_BYTES>>>(ah, al, Woh, Wol, bo, p, p2, p3,
                                          DMODEL, DMODEL);
    ln_res_kernel<<<NTOK, blk>>>(p, p2, p3, x, ln1g, ln1b, x1, x1h, x1l);

    // FFN1 (GELU, bf16 split hidden)
    dim3 gF(FFND / 128, NTOK / 128);
    gemm_mma<2><<<gF, blk, GSMEM_BYTES>>>(x1h, x1l, W1h, W1l, b1,
                                          nullptr, hh, hl, FFND, DMODEL);
    // FFN2 (split-K x3) + residual LN2 -> out
    gemm_splitk<<<gS, blk, GSMEM_BYTES>>>(hh, hl, W2h, W2l, b2, f, f2, f3,
                                          DMODEL, FFND);
    ln_res_kernel<<<NTOK, blk>>>(f, f2, f3, x1, ln2g, ln2b, out, nullptr, nullptr);
}

// round 15
// speedup vs baseline: 1.0561x; 1.0456x over previous
#include <cuda_runtime.h>
#include <cuda_bf16.h>
#include <cuda_fp16.h>
#include <math.h>
#include <stdint.h>

// Problem constants
#define DMODEL 768
#define FFND   3072
#define SEQ    2048
#define BATCH  2
#define NTOK   4096
#define NHEAD  12
#define HDIM   64

typedef __nv_bfloat16 bf16;

// ---------------------------------------------------------------------------
// Scratch (__device__ globals; no allocations allowed)
// ---------------------------------------------------------------------------
__device__ float g_p [NTOK * DMODEL];
__device__ float g_p2[NTOK * DMODEL];
__device__ float g_p3[NTOK * DMODEL];
__device__ float g_x1[NTOK * DMODEL];
__device__ float g_f [NTOK * DMODEL];
__device__ float g_f2[NTOK * DMODEL];
__device__ float g_f3[NTOK * DMODEL];
__device__ float g_zero[DMODEL];          // zero-initialized, never written

__device__ bf16 g_xh [NTOK * DMODEL], g_xl [NTOK * DMODEL];
__device__ bf16 g_qh [NTOK * DMODEL], g_ql [NTOK * DMODEL];
__device__ bf16 g_kh [NTOK * DMODEL], g_kl [NTOK * DMODEL];
__device__ bf16 g_vh [NTOK * DMODEL], g_vl [NTOK * DMODEL];  // holds fp16 bits
__device__ bf16 g_ah [NTOK * DMODEL], g_al [NTOK * DMODEL];
__device__ bf16 g_x1h[NTOK * DMODEL], g_x1l[NTOK * DMODEL];
__device__ bf16 g_hh [NTOK * FFND],   g_hl [NTOK * FFND];
__device__ bf16 g_Wqh[DMODEL*DMODEL], g_Wql[DMODEL*DMODEL];
__device__ bf16 g_Wkh[DMODEL*DMODEL], g_Wkl[DMODEL*DMODEL];
__device__ bf16 g_Wvh[DMODEL*DMODEL], g_Wvl[DMODEL*DMODEL];
__device__ bf16 g_Woh[DMODEL*DMODEL], g_Wol[DMODEL*DMODEL];
__device__ bf16 g_W1h[FFND*DMODEL],   g_W1l[FFND*DMODEL];
__device__ bf16 g_W2h[DMODEL*FFND],   g_W2l[DMODEL*FFND];

// ---------------------------------------------------------------------------
// PTX helpers (sm_103 base target safe)
// ---------------------------------------------------------------------------
__device__ __forceinline__ uint32_t smem_u32(const void* p) {
    uint32_t a;
    asm("{ .reg .u64 t; cvta.to.shared.u64 t, %1; cvt.u32.u64 %0, t; }"
        : "=r"(a) : "l"(p));
    return a;
}

#define CP16(dst, src) \
    asm volatile("cp.async.cg.shared.global [%0], [%1], 16;" :: "r"(dst), "l"(src))
#define CP_COMMIT() asm volatile("cp.async.commit_group;" ::: "memory")
#define CP_WAIT0()  asm volatile("cp.async.wait_group 0;" ::: "memory")
#define CP_WAIT1()  asm volatile("cp.async.wait_group 1;" ::: "memory")

__device__ __forceinline__ void ldsm4(uint32_t a, uint32_t& r0, uint32_t& r1,
                                      uint32_t& r2, uint32_t& r3) {
    asm volatile("ldmatrix.sync.aligned.m8n8.x4.shared.b16 {%0,%1,%2,%3}, [%4];"
                 : "=r"(r0), "=r"(r1), "=r"(r2), "=r"(r3) : "r"(a));
}
__device__ __forceinline__ void ldsm4t(uint32_t a, uint32_t& r0, uint32_t& r1,
                                       uint32_t& r2, uint32_t& r3) {
    asm volatile("ldmatrix.sync.aligned.m8n8.x4.trans.shared.b16 {%0,%1,%2,%3}, [%4];"
                 : "=r"(r0), "=r"(r1), "=r"(r2), "=r"(r3) : "r"(a));
}

__device__ __forceinline__ void mma16816(float* d, const uint32_t* a,
                                         uint32_t b0, uint32_t b1) {
    asm volatile("mma.sync.aligned.m16n8k16.row.col.f32.bf16.bf16.f32 "
                 "{%0,%1,%2,%3}, {%4,%5,%6,%7}, {%8,%9}, {%0,%1,%2,%3};"
                 : "+f"(d[0]), "+f"(d[1]), "+f"(d[2]), "+f"(d[3])
                 : "r"(a[0]), "r"(a[1]), "r"(a[2]), "r"(a[3]), "r"(b0), "r"(b1));
}

// fp16 variant (for P @ V)
__device__ __forceinline__ void mma16816h(float* d, const uint32_t* a,
                                          uint32_t b0, uint32_t b1) {
    asm volatile("mma.sync.aligned.m16n8k16.row.col.f32.f16.f16.f32 "
                 "{%0,%1,%2,%3}, {%4,%5,%6,%7}, {%8,%9}, {%0,%1,%2,%3};"
                 : "+f"(d[0]), "+f"(d[1]), "+f"(d[2]), "+f"(d[3])
                 : "r"(a[0]), "r"(a[1]), "r"(a[2]), "r"(a[3]), "r"(b0), "r"(b1));
}

// fast exp2
__device__ __forceinline__ float fexp2(float x) {
    float y;
    asm("ex2.approx.f32 %0, %1;" : "=f"(y) : "f"(x));
    return y;
}

// split two floats -> packed bf16x2 (hi) and bf16x2 (lo), 1-instr packing
__device__ __forceinline__ void split2(float a, float b, uint32_t& hi, uint32_t& lo) {
    asm("cvt.rn.bf16x2.f32 %0, %1, %2;" : "=r"(hi) : "f"(b), "f"(a));
    float ha = __uint_as_float(hi << 16);
    float hb = __uint_as_float(hi & 0xffff0000u);
    asm("cvt.rn.bf16x2.f32 %0, %1, %2;" : "=r"(lo) : "f"(b - hb), "f"(a - ha));
}

// pack two floats into fp16x2 bits
__device__ __forceinline__ uint32_t pack_h2(float a, float b) {
    __half2 h = __floats2half2_rn(a, b);
    return *(uint32_t*)&h;
}

// ---------------------------------------------------------------------------
// Merged split conversion, MLP=4: each thread loads 4 independent float4s.
// ---------------------------------------------------------------------------
#define CB_X   (NTOK*DMODEL/4096)           // 768
#define CB_W   (DMODEL*DMODEL/4096)         // 144
#define CB_F   (FFND*DMODEL/4096)           // 576
#define CB_TOTAL (CB_X + 4*CB_W + 2*CB_F)   // 2496

__global__ void __launch_bounds__(256) cvt_all_kernel(
    const float* __restrict__ x,
    const float* __restrict__ Wq, const float* __restrict__ Wk,
    const float* __restrict__ Wv, const float* __restrict__ Wo,
    const float* __restrict__ W1, const float* __restrict__ W2,
    bf16* __restrict__ xh,  bf16* __restrict__ xl,
    bf16* __restrict__ Wqh, bf16* __restrict__ Wql,
    bf16* __restrict__ Wkh, bf16* __restrict__ Wkl,
    bf16* __restrict__ Wvh, bf16* __restrict__ Wvl,
    bf16* __restrict__ Woh, bf16* __restrict__ Wol,
    bf16* __restrict__ W1h, bf16* __restrict__ W1l,
    bf16* __restrict__ W2h, bf16* __restrict__ W2l)
{
    int bi = blockIdx.x;
    const float* in; bf16 *hi, *lo; int base;
    if      (bi < CB_X)            { in = x;  hi = xh;  lo = xl;  base = 0; }
    else if (bi < CB_X + CB_W)     { in = Wq; hi = Wqh; lo = Wql; base = CB_X; }
    else if (bi < CB_X + 2*CB_W)   { in = Wk; hi = Wkh; lo = Wkl; base = CB_X + CB_W; }
    else if (bi < CB_X + 3*CB_W)   { in = Wv; hi = Wvh; lo = Wvl; base = CB_X + 2*CB_W; }
    else if (bi < CB_X + 4*CB_W)   { in = Wo; hi = Woh; lo = Wol; base = CB_X + 3*CB_W; }
    else if (bi < CB_X + 4*CB_W + CB_F)
                                   { in = W1; hi = W1h; lo = W1l; base = CB_X + 4*CB_W; }
    else                           { in = W2; hi = W2h; lo = W2l; base = CB_X + 4*CB_W + CB_F; }

    size_t e0 = (size_t)(bi - base) * 1024 + threadIdx.x;   // float4 index
    const float4* in4 = (const float4*)in;
    float4 v[4];
    #pragma unroll
    for (int j = 0; j < 4; j++) v[j] = in4[e0 + j * 256];   // 4 independent loads
    #pragma unroll
    for (int j = 0; j < 4; j++) {
        uint32_t h0, l0, h1, l1;
        split2(v[j].x, v[j].y, h0, l0);
        split2(v[j].z, v[j].w, h1, l1);
        size_t idx = (e0 + (size_t)j * 256) * 4;
        *(uint2*)(hi + idx) = make_uint2(h0, h1);
        *(uint2*)(lo + idx) = make_uint2(l0, l1);
    }
}

// ---------------------------------------------------------------------------
// Shared GEMM body (R8-measured structure): 128x128 tile, BK=32 (64B rows),
// 8 warps, 3-stage cp.async pipeline, 2 CTAs/SM. 3 MMA terms (hh, hl, lh).
// MODE 0: fp32 C + bias.  MODE 1: bf16 split out, (acc+bias)*scale.
// MODE 2: GELU -> bf16 split out.  MODE 4: fp16 split out (for V).
// ---------------------------------------------------------------------------
#define GSTAGE 32768                       // 4 matrices x 8KB
#define GSMEM_BYTES (3*GSTAGE + 1024)      // 99328 -> 2 CTA/SM

template<int MODE>
__device__ __forceinline__ void gemm_body(
    const bf16* __restrict__ Ah, const bf16* __restrict__ Al,
    const bf16* __restrict__ Bh, const bf16* __restrict__ Bl,
    const float* __restrict__ bias,
    float* __restrict__ C, bf16* __restrict__ Ch, bf16* __restrict__ Cl,
    int N, int ldk, int kIter, int k0, float scale, int m0, int n0)
{
    extern __shared__ __align__(1024) char smem_raw[];
    uint32_t sb = smem_u32(smem_raw);
    sb = (sb + 1023) & ~1023u;

    const int tid  = threadIdx.x;
    const int lane = tid & 31, wid = tid >> 5;
    const int wm = wid & 3, wn = wid >> 2;

    float acc[2][8][4];
    #pragma unroll
    for (int i = 0; i < 2; i++)
        #pragma unroll
        for (int j = 0; j < 8; j++)
            #pragma unroll
            for (int q = 0; q < 4; q++) acc[i][j][q] = 0.f;

    const int lrow = tid >> 1;
    const int c2   = (tid & 1) * 2;
    const bf16* pAh = Ah + (size_t)(m0 + lrow) * ldk + k0;
    const bf16* pAl = Al + (size_t)(m0 + lrow) * ldk + k0;
    const bf16* pBh = Bh + (size_t)(n0 + lrow) * ldk + k0;
    const bf16* pBl = Bl + (size_t)(n0 + lrow) * ldk + k0;
    const uint32_t swr = (uint32_t)((lrow >> 1) & 3);

    auto load_stage = [&](int s, int kt) {
        uint32_t st = sb + s * GSTAGE + lrow * 64;
        size_t ko = (size_t)kt * 32;
        #pragma unroll
        for (int cc = 0; cc < 2; cc++) {
            int c = c2 + cc;
            uint32_t off = (uint32_t)((c ^ swr) << 4);
            CP16(st + off,         pAh + ko + c * 8);
            CP16(st + 8192 + off,  pAl + ko + c * 8);
            CP16(st + 16384 + off, pBh + ko + c * 8);
            CP16(st + 24576 + off, pBl + ko + c * 8);
        }
    };

    const int nk = kIter >> 5;       // k32 tiles, always >= 4 here
    load_stage(0, 0); CP_COMMIT();
    load_stage(1, 1); CP_COMMIT();

    const int l15 = lane & 15, lh = lane >> 4;
    const int arowbase = wm * 32 + l15;
    const int browbase = wn * 64 + l15;
    int slot = 0, nslot = 2;

    for (int kt = 0; kt < nk; kt++) {
        if (kt + 1 < nk) CP_WAIT1(); else CP_WAIT0();
        __syncthreads();
        if (kt + 2 < nk) {
            load_stage(nslot, kt + 2);
            CP_COMMIT();
        }
        uint32_t st = sb + slot * GSTAGE;

        #pragma unroll
        for (int ks = 0; ks < 2; ks++) {
            const int chunk = ks * 2 + lh;
            uint32_t ah[2][4], al[2][4];
            #pragma unroll
            for (int mi = 0; mi < 2; mi++) {
                int row = arowbase + mi * 16;
                uint32_t ad = st + row * 64 + ((chunk ^ ((row >> 1) & 3)) << 4);
                ldsm4(ad,        ah[mi][0], ah[mi][1], ah[mi][2], ah[mi][3]);
                ldsm4(ad + 8192, al[mi][0], al[mi][1], al[mi][2], al[mi][3]);
            }
            uint32_t bh[2][4], bl[2][4];
            {
                uint32_t bd = st + 16384 + browbase * 64
                            + ((chunk ^ ((browbase >> 1) & 3)) << 4);
                ldsm4(bd,        bh[0][0], bh[0][1], bh[0][2], bh[0][3]);
                ldsm4(bd + 8192, bl[0][0], bl[0][1], bl[0][2], bl[0][3]);
            }
            #pragma unroll
            for (int g = 0; g < 4; g++) {
                const int cur = g & 1;
                if (g < 3) {
                    int row = browbase + (g + 1) * 16;
                    uint32_t bd = st + 16384 + row * 64
                                + ((chunk ^ ((row >> 1) & 3)) << 4);
                    ldsm4(bd,        bh[cur^1][0], bh[cur^1][1],
                                     bh[cur^1][2], bh[cur^1][3]);
                    ldsm4(bd + 8192, bl[cur^1][0], bl[cur^1][1],
                                     bl[cur^1][2], bl[cur^1][3]);
                }
                #pragma unroll
                for (int mi = 0; mi < 2; mi++) {
                    mma16816(acc[mi][2*g],   ah[mi], bh[cur][0], bh[cur][2]);
                    mma16816(acc[mi][2*g],   ah[mi], bl[cur][0], bl[cur][2]);
                    mma16816(acc[mi][2*g],   al[mi], bh[cur][0], bh[cur][2]);
                    mma16816(acc[mi][2*g+1], ah[mi], bh[cur][1], bh[cur][3]);
                    mma16816(acc[mi][2*g+1], ah[mi], bl[cur][1], bl[cur][3]);
                    mma16816(acc[mi][2*g+1], al[mi], bh[cur][1], bh[cur][3]);
                }
            }
        }
        slot = (slot == 2) ? 0 : slot + 1;
        nslot = (nslot == 2) ? 0 : nslot + 1;
    }

    const int g4 = lane >> 2, t4 = lane & 3;
    #pragma unroll
    for (int mi = 0; mi < 2; mi++) {
        #pragma unroll
        for (int n = 0; n < 8; n++) {
            int row = m0 + wm * 32 + mi * 16 + g4;
            int col = n0 + wn * 64 + n * 8 + t4 * 2;
            float b0 = bias[col], b1 = bias[col + 1];
            float v00 = acc[mi][n][0] + b0, v01 = acc[mi][n][1] + b1;
            float v10 = acc[mi][n][2] + b0, v11 = acc[mi][n][3] + b1;
            if (MODE == 0) {
                *(float2*)(C + (size_t)row * N + col)       = make_float2(v00, v01);
                *(float2*)(C + (size_t)(row + 8) * N + col) = make_float2(v10, v11);
            } else if (MODE == 4) {
                // fp16 hi/lo split output (V path)
                __half2 H0 = __floats2half2_rn(v00, v01);
                __half2 H1 = __floats2half2_rn(v10, v11);
                __half2 L0 = __floats2half2_rn(v00 - __low2float(H0),
                                               v01 - __high2float(H0));
                __half2 L1 = __floats2half2_rn(v10 - __low2float(H1),
                                               v11 - __high2float(H1));
                *(uint32_t*)(Ch + (size_t)row * N + col)       = *(uint32_t*)&H0;
                *(uint32_t*)(Ch + (size_t)(row + 8) * N + col) = *(uint32_t*)&H1;
                *(uint32_t*)(Cl + (size_t)row * N + col)       = *(uint32_t*)&L0;
                *(uint32_t*)(Cl + (size_t)(row + 8) * N + col) = *(uint32_t*)&L1;
            } else {
                if (MODE == 1) {
                    v00 *= scale; v01 *= scale; v10 *= scale; v11 *= scale;
                } else {
                    v00 = 0.5f * v00 * (1.0f + erff(v00 * 0.70710678118654752f));
                    v01 = 0.5f * v01 * (1.0f + erff(v01 * 0.70710678118654752f));
                    v10 = 0.5f * v10 * (1.0f + erff(v10 * 0.70710678118654752f));
                    v11 = 0.5f * v11 * (1.0f + erff(v11 * 0.70710678118654752f));
                }
                uint32_t h0, l0, h1, l1;
                split2(v00, v01, h0, l0);
                split2(v10, v11, h1, l1);
                *(uint32_t*)(Ch + (size_t)row * N + col)       = h0;
                *(uint32_t*)(Ch + (size_t)(row + 8) * N + col) = h1;
                *(uint32_t*)(Cl + (size_t)row * N + col)       = l0;
                *(uint32_t*)(Cl + (size_t)(row + 8) * N + col) = l1;
            }
        }
    }
}

template<int MODE>
__global__ void __launch_bounds__(256, 2) gemm_mma(
    const bf16* __restrict__ Ah, const bf16* __restrict__ Al,
    const bf16* __restrict__ Bh, const bf16* __restrict__ Bl,
    const float* __restrict__ bias,
    float* __restrict__ C, bf16* __restrict__ Ch, bf16* __restrict__ Cl,
    int N, int K)
{
    gemm_body<MODE>(Ah, Al, Bh, Bl, bias, C, Ch, Cl, N, K, K, 0, 1.0f,
                    blockIdx.y * 128, blockIdx.x * 128);
}

// Split-K x3 (fp32 output): z=0 -> C0 (+bias), z=1 -> C1, z=2 -> C2.
__global__ void __launch_bounds__(256, 2) gemm_splitk(
    const bf16* __restrict__ Ah, const bf16* __restrict__ Al,
    const bf16* __restrict__ Bh, const bf16* __restrict__ Bl,
    const float* __restrict__ bias,
    float* __restrict__ C0, float* __restrict__ C1, float* __restrict__ C2,
    int N, int K)
{
    int z = blockIdx.z;
    int kh = K / 3;
    float* Cz = (z == 0) ? C0 : (z == 1) ? C1 : C2;
    gemm_body<0>(Ah, Al, Bh, Bl, z ? g_zero : bias, Cz,
                 nullptr, nullptr, N, K, kh, z * kh, 1.0f,
                 blockIdx.y * 128, blockIdx.x * 128);
}

// Combined QKV; Q pre-scaled by 0.125*log2(e); V emitted as fp16 split.
#define QSCALE (0.125f * 1.4426950408889634f)
__global__ void __launch_bounds__(256, 2) gemm_qkv(
    const bf16* __restrict__ Ah, const bf16* __restrict__ Al,
    const bf16* __restrict__ Wqh, const bf16* __restrict__ Wql,
    const bf16* __restrict__ Wkh, const bf16* __restrict__ Wkl,
    const bf16* __restrict__ Wvh, const bf16* __restrict__ Wvl,
    const float* __restrict__ bq, const float* __restrict__ bk,
    const float* __restrict__ bv,
    bf16* __restrict__ qh, bf16* __restrict__ ql,
    bf16* __restrict__ kh, bf16* __restrict__ kl,
    bf16* __restrict__ vh, bf16* __restrict__ vl)
{
    int z = blockIdx.z;
    if (z == 2) {
        gemm_body<4>(Ah, Al, Wvh, Wvl, bv, nullptr, vh, vl,
                     DMODEL, DMODEL, DMODEL, 0, 1.0f,
                     blockIdx.y * 128, blockIdx.x * 128);
    } else {
        const bf16* Bh = (z == 0) ? Wqh : Wkh;
        const bf16* Bl = (z == 0) ? Wql : Wkl;
        const float* bias = (z == 0) ? bq : bk;
        bf16* Ch = (z == 0) ? qh : kh;
        bf16* Cl = (z == 0) ? ql : kl;
        float scale = (z == 0) ? QSCALE : 1.0f;
        gemm_body<1>(Ah, Al, Bh, Bl, bias, nullptr, Ch, Cl,
                     DMODEL, DMODEL, DMODEL, 0, scale,
                     blockIdx.y * 128, blockIdx.x * 128);
    }
}

// ---------------------------------------------------------------------------
// Flash attention: Q-tile 128, key-tile 64, 2-stage KV, exp2 softmax.
// S = 3-term bf16 (near-exact). P@V = fp16: single-fp16 P x (vh+vl fp16 split)
// -> 2 terms, 64 MMAs/kt instead of 96.
// ---------------------------------------------------------------------------
#define ASMEM_BYTES (32768 + 2*32768 + 1024)

__global__ void __launch_bounds__(256, 2) attn_mma(
    const bf16* __restrict__ Qh, const bf16* __restrict__ Ql,
    const bf16* __restrict__ Kh, const bf16* __restrict__ Kl,
    const bf16* __restrict__ Vh, const bf16* __restrict__ Vl,  // fp16 bits
    bf16* __restrict__ Oh, bf16* __restrict__ Ol)
{
    extern __shared__ __align__(1024) char smem_raw[];
    uint32_t sb = smem_u32(smem_raw);
    sb = (sb + 1023) & ~1023u;

    const int tid  = threadIdx.x;
    const int lane = tid & 31, wq = tid >> 5;
    const int l15 = lane & 15, lh = lane >> 4;
    const int g4 = lane >> 2, t4 = lane & 3;
    const int b = blockIdx.z, h = blockIdx.y;
    const int q0 = blockIdx.x * 128;
    const size_t hoff = (size_t)h * HDIM;

    {
        int qrow = tid >> 1;
        int cb = (tid & 1) * 4;
        size_t gidx = ((size_t)(b * SEQ + q0 + qrow)) * DMODEL + hoff;
        uint32_t st = sb + qrow * 128;
        #pragma unroll
        for (int c = 0; c < 4; c++) {
            uint32_t ph = (uint32_t)(((cb + c) ^ (qrow & 7)) << 4);
            CP16(st + ph,         Qh + gidx + (cb + c) * 8);
            CP16(st + 16384 + ph, Ql + gidx + (cb + c) * 8);
        }
    }
    CP_COMMIT();

    const int krow = tid >> 2;
    const int kc0  = (tid & 3) * 2;
    auto load_kv = [&](int s, int kt) {
        uint32_t base = sb + 32768 + s * 32768;
        size_t gidx = ((size_t)(b * SEQ + kt * 64 + krow)) * DMODEL + hoff;
        #pragma unroll
        for (int cc = 0; cc < 2; cc++) {
            int c = kc0 + cc;
            uint32_t off = krow * 128 + ((c ^ (krow & 7)) << 4);
            CP16(base + off,         Kh + gidx + c * 8);
            CP16(base + 8192 + off,  Kl + gidx + c * 8);
            CP16(base + 16384 + off, Vh + gidx + c * 8);
            CP16(base + 24576 + off, Vl + gidx + c * 8);
        }
    };
    load_kv(0, 0);
    CP_COMMIT();

    float m0 = -1e30f, m1 = -1e30f, l0 = 0.f, l1 = 0.f;
    float o[8][4];
    #pragma unroll
    for (int j = 0; j < 8; j++)
        #pragma unroll
        for (int q = 0; q < 4; q++) o[j][q] = 0.f;

    const int NT = SEQ / 64;
    for (int kt = 0; kt < NT; kt++) {
        CP_WAIT0();
        __syncthreads();
        if (kt + 1 < NT) {
            load_kv((kt + 1) & 1, kt + 1);
            CP_COMMIT();
        }

        uint32_t stb = sb + 32768 + (kt & 1) * 32768;

        float s[8][4];
        #pragma unroll
        for (int j = 0; j < 8; j++)
            #pragma unroll
            for (int q = 0; q < 4; q++) s[j][q] = 0.f;

        #pragma unroll
        for (int kc = 0; kc < 4; kc++) {
            const int chunk = kc * 2 + lh;
            int arow = wq * 16 + l15;
            uint32_t aaddr = sb + arow * 128 + ((chunk ^ (arow & 7)) << 4);
            uint32_t qh_[4], ql_[4];
            ldsm4(aaddr,         qh_[0], qh_[1], qh_[2], qh_[3]);
            ldsm4(aaddr + 16384, ql_[0], ql_[1], ql_[2], ql_[3]);
            #pragma unroll
            for (int g = 0; g < 4; g++) {
                int brow = g * 16 + l15;
                uint32_t baddr = stb + brow * 128 + ((chunk ^ (brow & 7)) << 4);
                uint32_t kh_[4], kl_[4];
                ldsm4(baddr,        kh_[0], kh_[1], kh_[2], kh_[3]);
                ldsm4(baddr + 8192, kl_[0], kl_[1], kl_[2], kl_[3]);
                mma16816(s[2*g],   qh_, kh_[0], kh_[2]);
                mma16816(s[2*g],   qh_, kl_[0], kl_[2]);
                mma16816(s[2*g],   ql_, kh_[0], kh_[2]);
                mma16816(s[2*g+1], qh_, kh_[1], kh_[3]);
                mma16816(s[2*g+1], qh_, kl_[1], kl_[3]);
                mma16816(s[2*g+1], ql_, kh_[1], kh_[3]);
            }
        }

        float mx0 = -1e30f, mx1 = -1e30f;
        #pragma unroll
        for (int j = 0; j < 8; j++) {
            mx0 = fmaxf(mx0, fmaxf(s[j][0], s[j][1]));
            mx1 = fmaxf(mx1, fmaxf(s[j][2], s[j][3]));
        }
        mx0 = fmaxf(mx0, __shfl_xor_sync(0xffffffffu, mx0, 1));
        mx0 = fmaxf(mx0, __shfl_xor_sync(0xffffffffu, mx0, 2));
        mx1 = fmaxf(mx1, __shfl_xor_sync(0xffffffffu, mx1, 1));
        mx1 = fmaxf(mx1, __shfl_xor_sync(0xffffffffu, mx1, 2));

        float mn0 = fmaxf(m0, mx0), mn1 = fmaxf(m1, mx1);
        float a0 = fexp2(m0 - mn0), a1 = fexp2(m1 - mn1);
        m0 = mn0; m1 = mn1;

        float sum0 = 0.f, sum1 = 0.f;
        #pragma unroll
        for (int j = 0; j < 8; j++) {
            s[j][0] = fexp2(s[j][0] - mn0);
            s[j][1] = fexp2(s[j][1] - mn0);
            s[j][2] = fexp2(s[j][2] - mn1);
            s[j][3] = fexp2(s[j][3] - mn1);
            sum0 += s[j][0] + s[j][1];
            sum1 += s[j][2] + s[j][3];
        }
        sum0 += __shfl_xor_sync(0xffffffffu, sum0, 1);
        sum0 += __shfl_xor_sync(0xffffffffu, sum0, 2);
        sum1 += __shfl_xor_sync(0xffffffffu, sum1, 1);
        sum1 += __shfl_xor_sync(0xffffffffu, sum1, 2);
        l0 = l0 * a0 + sum0;
        l1 = l1 * a1 + sum1;

        #pragma unroll
        for (int j = 0; j < 8; j++) {
            o[j][0] *= a0; o[j][1] *= a0;
            o[j][2] *= a1; o[j][3] *= a1;
        }

        // ---- O += P @ V: single-fp16 P, fp16-split V (2 terms) ----
        #pragma unroll
        for (int kc = 0; kc < 4; kc++) {
            uint32_t ph_[4];
            ph_[0] = pack_h2(s[2*kc][0],   s[2*kc][1]);
            ph_[1] = pack_h2(s[2*kc][2],   s[2*kc][3]);
            ph_[2] = pack_h2(s[2*kc+1][0], s[2*kc+1][1]);
            ph_[3] = pack_h2(s[2*kc+1][2], s[2*kc+1][3]);

            int vrow = kc * 16 + (lane & 7) + ((lane >> 3) & 1) * 8;
            #pragma unroll
            for (int nn = 0; nn < 4; nn++) {
                int colchunk = nn * 2 + (lane >> 4);
                uint32_t vaddr = stb + 16384 + vrow * 128
                               + ((colchunk ^ (vrow & 7)) << 4);
                uint32_t vh_[4], vl_[4];
                ldsm4t(vaddr,        vh_[0], vh_[1], vh_[2], vh_[3]);
                ldsm4t(vaddr + 8192, vl_[0], vl_[1], vl_[2], vl_[3]);
                mma16816h(o[2*nn],   ph_, vh_[0], vh_[1]);
                mma16816h(o[2*nn],   ph_, vl_[0], vl_[1]);
                mma16816h(o[2*nn+1], ph_, vh_[2], vh_[3]);
                mma16816h(o[2*nn+1], ph_, vl_[2], vl_[3]);
            }
        }
    }

    float i0 = 1.0f / l0, i1 = 1.0f / l1;
    int row0 = b * SEQ + q0 + wq * 16 + g4;
    #pragma unroll
    for (int j = 0; j < 8; j++) {
        int col = (int)hoff + j * 8 + t4 * 2;
        uint32_t h0, lo0, h1, lo1;
        split2(o[j][0] * i0, o[j][1] * i0, h0, lo0);
        split2(o[j][2] * i1, o[j][3] * i1, h1, lo1);
        *(uint32_t*)(Oh + (size_t)row0 * DMODEL + col)       = h0;
        *(uint32_t*)(Ol + (size_t)row0 * DMODEL + col)       = lo0;
        *(uint32_t*)(Oh + (size_t)(row0 + 8) * DMODEL + col) = h1;
        *(uint32_t*)(Ol + (size_t)(row0 + 8) * DMODEL + col) = lo1;
    }
}

// ---------------------------------------------------------------------------
// Fused residual add + LayerNorm over (y0 + y1 + y2 + residual).
// ---------------------------------------------------------------------------
__global__ void __launch_bounds__(256) ln_res_kernel(
    const float* __restrict__ y0, const float* __restrict__ y1,
    const float* __restrict__ y2, const float* __restrict__ r,
    const float* __restrict__ g, const float* __restrict__ b,
    float* __restrict__ o, bf16* __restrict__ oh, bf16* __restrict__ ol)
{
    const int row = blockIdx.x;
    const int tid = threadIdx.x;
    const float* y0p = y0 + (size_t)row * DMODEL;
    const float* y1p = y1 + (size_t)row * DMODEL;
    const float* y2p = y2 + (size_t)row * DMODEL;
    const float* rp  = r  + (size_t)row * DMODEL;

    float v[3];
    float s = 0.f, ss = 0.f;
    #pragma unroll
    for (int j = 0; j < 3; j++) {
        int c = tid + j * 256;
        float a = y0p[c] + y1p[c] + y2p[c] + rp[c];
        v[j] = a; s += a; ss += a * a;
    }
    #pragma unroll
    for (int off = 16; off; off >>= 1) {
        s  += __shfl_xor_sync(0xffffffffu, s, off);
        ss += __shfl_xor_sync(0xffffffffu, ss, off);
    }
    __shared__ float sred[16];
    if ((tid & 31) == 0) { sred[tid >> 5] = s; sred[8 + (tid >> 5)] = ss; }
    __syncthreads();
    if (tid == 0) {
        float S = 0.f, SS = 0.f;
        #pragma unroll
        for (int w = 0; w < 8; w++) { S += sred[w]; SS += sred[8 + w]; }
        sred[0] = S * (1.0f / DMODEL);
        sred[1] = SS * (1.0f / DMODEL);
    }
    __syncthreads();
    float mu  = sred[0];
    float var = sred[1] - mu * mu;
    float rstd = rsqrtf(var + 1e-5f);
    float* op = o + (size_t)row * DMODEL;
    #pragma unroll
    for (int j = 0; j < 3; j++) {
        int c = tid + j * 256;
        float val = (v[j] - mu) * rstd * g[c] + b[c];
        op[c] = val;
        if (oh) {
            bf16 hv = __float2bfloat16(val);
            oh[(size_t)row * DMODEL + c] = hv;
            ol[(size_t)row * DMODEL + c] =
                __float2bfloat16(val - __bfloat162float(hv));
        }
    }
}

// ---------------------------------------------------------------------------
extern "C" void kernel_launch(void* const* d_in, const int* in_sizes, int n_in,
                              void* d_out, int out_size)
{
    const float* x     = (const float*)d_in[0];
    const float* Wq    = (const float*)d_in[1];
    const float* bq    = (const float*)d_in[2];
    const float* Wk    = (const float*)d_in[3];
    const float* bk    = (const float*)d_in[4];
    const float* Wv    = (const float*)d_in[5];
    const float* bv    = (const float*)d_in[6];
    const float* Wo    = (const float*)d_in[7];
    const float* bo    = (const float*)d_in[8];
    const float* ln1g  = (const float*)d_in[9];
    const float* ln1b  = (const float*)d_in[10];
    const float* ln2g  = (const float*)d_in[11];
    const float* ln2b  = (const float*)d_in[12];
    const float* W1    = (const float*)d_in[13];
    const float* b1    = (const float*)d_in[14];
    const float* W2    = (const float*)d_in[15];
    const float* b2    = (const float*)d_in[16];
    float* out = (float*)d_out;

    float *p, *p2, *p3, *x1, *f, *f2, *f3;
    cudaGetSymbolAddress((void**)&p,  g_p);
    cudaGetSymbolAddress((void**)&p2, g_p2);
    cudaGetSymbolAddress((void**)&p3, g_p3);
    cudaGetSymbolAddress((void**)&x1, g_x1);
    cudaGetSymbolAddress((void**)&f,  g_f);
    cudaGetSymbolAddress((void**)&f2, g_f2);
    cudaGetSymbolAddress((void**)&f3, g_f3);

    bf16 *xh,*xl,*qh,*ql,*kh,*kl,*vh,*vl,*ah,*al,*x1h,*x1l,*hh,*hl;
    bf16 *Wqh,*Wql,*Wkh,*Wkl,*Wvh,*Wvl,*Woh,*Wol,*W1h,*W1l,*W2h,*W2l;
    cudaGetSymbolAddress((void**)&xh,  g_xh);  cudaGetSymbolAddress((void**)&xl,  g_xl);
    cudaGetSymbolAddress((void**)&qh,  g_qh);  cudaGetSymbolAddress((void**)&ql,  g_ql);
    cudaGetSymbolAddress((void**)&kh,  g_kh);  cudaGetSymbolAddress((void**)&kl,  g_kl);
    cudaGetSymbolAddress((void**)&vh,  g_vh);  cudaGetSymbolAddress((void**)&vl,  g_vl);
    cudaGetSymbolAddress((void**)&ah,  g_ah);  cudaGetSymbolAddress((void**)&al,  g_al);
    cudaGetSymbolAddress((void**)&x1h, g_x1h); cudaGetSymbolAddress((void**)&x1l, g_x1l);
    cudaGetSymbolAddress((void**)&hh,  g_hh);  cudaGetSymbolAddress((void**)&hl,  g_hl);
    cudaGetSymbolAddress((void**)&Wqh, g_Wqh); cudaGetSymbolAddress((void**)&Wql, g_Wql);
    cudaGetSymbolAddress((void**)&Wkh, g_Wkh); cudaGetSymbolAddress((void**)&Wkl, g_Wkl);
    cudaGetSymbolAddress((void**)&Wvh, g_Wvh); cudaGetSymbolAddress((void**)&Wvl, g_Wvl);
    cudaGetSymbolAddress((void**)&Woh, g_Woh); cudaGetSymbolAddress((void**)&Wol, g_Wol);
    cudaGetSymbolAddress((void**)&W1h, g_W1h); cudaGetSymbolAddress((void**)&W1l, g_W1l);
    cudaGetSymbolAddress((void**)&W2h, g_W2h); cudaGetSymbolAddress((void**)&W2l, g_W2l);

    cudaFuncSetAttribute(gemm_mma<2>,
                         cudaFuncAttributeMaxDynamicSharedMemorySize, GSMEM_BYTES);
    cudaFuncSetAttribute(gemm_splitk,
                         cudaFuncAttributeMaxDynamicSharedMemorySize, GSMEM_BYTES);
    cudaFuncSetAttribute(gemm_qkv,
                         cudaFuncAttributeMaxDynamicSharedMemorySize, GSMEM_BYTES);
    cudaFuncSetAttribute(attn_mma,
                         cudaFuncAttributeMaxDynamicSharedMemorySize, ASMEM_BYTES);

    dim3 blk(256);

    // Merged split conversion, MLP=4
    cvt_all_kernel<<<CB_TOTAL, blk>>>(x, Wq, Wk, Wv, Wo, W1, W2,
                                      xh, xl, Wqh, Wql, Wkh, Wkl, Wvh, Wvl,
                                      Woh, Wol, W1h, W1l, W2h, W2l);

    // QKV combined (Q/K bf16 split, V fp16 split; Q pre-scaled)
    dim3 gqkv(DMODEL / 128, NTOK / 128, 3);
    gemm_qkv<<<gqkv, blk, GSMEM_BYTES>>>(xh, xl, Wqh, Wql, Wkh, Wkl, Wvh, Wvl,
                                         bq, bk, bv, qh, ql, kh, kl, vh, vl);

    // Attention (exp2-domain; fp16 P@V)
    dim3 ga(SEQ / 128, NHEAD, BATCH);
    attn_mma<<<ga, blk, ASMEM_BYTES>>>(qh, ql, kh, kl, vh, vl, ah, al);

    // Output projection (split-K x3) + residual LN1
    dim3 gS(DMODEL / 128, NTOK / 128, 3);
    gemm_splitk<<<gS, blk, GSMEM_BYTES>>>(ah, al, Woh, Wol, bo, p, p2, p3,
                                          DMODEL, DMODEL);
    ln_res_kernel<<<NTOK, blk>>>(p, p2, p3, x, ln1g, ln1b, x1, x1h, x1l);

    // FFN1 (GELU, bf16 split hidden)
    dim3 gF(FFND / 128, NTOK / 128);
    gemm_mma<2><<<gF, blk, GSMEM_BYTES>>>(x1h, x1l, W1h, W1l, b1,
                                          nullptr, hh, hl, FFND, DMODEL);
    // FFN2 (split-K x3) + residual LN2 -> out
    gemm_splitk<<<gS, blk, GSMEM_BYTES>>>(hh, hl, W2h, W2l, b2, f, f2, f3,
                                          DMODEL, FFND);
    ln_res_kernel<<<NTOK, blk>>>(f, f2, f3, x1, ln2g, ln2b, out, nullptr, nullptr);
}

// round 16
// speedup vs baseline: 1.0922x; 1.0342x over previous
#include <cuda_runtime.h>
#include <cuda_bf16.h>
#include <cuda_fp16.h>
#include <math.h>
#include <stdint.h>

// Problem constants
#define DMODEL 768
#define FFND   3072
#define SEQ    2048
#define BATCH  2
#define NTOK   4096
#define NHEAD  12
#define HDIM   64

typedef __nv_bfloat16 bf16;

// ---------------------------------------------------------------------------
// Scratch (__device__ globals; no allocations allowed)
// ---------------------------------------------------------------------------
__device__ float g_p [NTOK * DMODEL];
__device__ float g_p2[NTOK * DMODEL];
__device__ float g_p3[NTOK * DMODEL];
__device__ float g_x1[NTOK * DMODEL];
__device__ float g_f [NTOK * DMODEL];
__device__ float g_f2[NTOK * DMODEL];
__device__ float g_f3[NTOK * DMODEL];
__device__ float g_zero[DMODEL];          // zero-initialized, never written

__device__ bf16 g_xh [NTOK * DMODEL], g_xl [NTOK * DMODEL];
__device__ bf16 g_qh [NTOK * DMODEL], g_ql [NTOK * DMODEL];
__device__ bf16 g_kh [NTOK * DMODEL], g_kl [NTOK * DMODEL];
__device__ bf16 g_vh [NTOK * DMODEL];                        // single fp16 bits
__device__ bf16 g_ah [NTOK * DMODEL], g_al [NTOK * DMODEL];
__device__ bf16 g_x1h[NTOK * DMODEL], g_x1l[NTOK * DMODEL];
__device__ bf16 g_hh [NTOK * FFND],   g_hl [NTOK * FFND];
__device__ bf16 g_Wqh[DMODEL*DMODEL], g_Wql[DMODEL*DMODEL];
__device__ bf16 g_Wkh[DMODEL*DMODEL], g_Wkl[DMODEL*DMODEL];
__device__ bf16 g_Wvh[DMODEL*DMODEL], g_Wvl[DMODEL*DMODEL];
__device__ bf16 g_Woh[DMODEL*DMODEL], g_Wol[DMODEL*DMODEL];
__device__ bf16 g_W1h[FFND*DMODEL],   g_W1l[FFND*DMODEL];
__device__ bf16 g_W2h[DMODEL*FFND],   g_W2l[DMODEL*FFND];

// ---------------------------------------------------------------------------
// PTX helpers (sm_103 base target safe)
// ---------------------------------------------------------------------------
__device__ __forceinline__ uint32_t smem_u32(const void* p) {
    uint32_t a;
    asm("{ .reg .u64 t; cvta.to.shared.u64 t, %1; cvt.u32.u64 %0, t; }"
        : "=r"(a) : "l"(p));
    return a;
}

#define CP16(dst, src) \
    asm volatile("cp.async.cg.shared.global [%0], [%1], 16;" :: "r"(dst), "l"(src))
#define CP_COMMIT() asm volatile("cp.async.commit_group;" ::: "memory")
#define CP_WAIT0()  asm volatile("cp.async.wait_group 0;" ::: "memory")
#define CP_WAIT1()  asm volatile("cp.async.wait_group 1;" ::: "memory")

__device__ __forceinline__ void ldsm4(uint32_t a, uint32_t& r0, uint32_t& r1,
                                      uint32_t& r2, uint32_t& r3) {
    asm volatile("ldmatrix.sync.aligned.m8n8.x4.shared.b16 {%0,%1,%2,%3}, [%4];"
                 : "=r"(r0), "=r"(r1), "=r"(r2), "=r"(r3) : "r"(a));
}
__device__ __forceinline__ void ldsm4t(uint32_t a, uint32_t& r0, uint32_t& r1,
                                       uint32_t& r2, uint32_t& r3) {
    asm volatile("ldmatrix.sync.aligned.m8n8.x4.trans.shared.b16 {%0,%1,%2,%3}, [%4];"
                 : "=r"(r0), "=r"(r1), "=r"(r2), "=r"(r3) : "r"(a));
}

__device__ __forceinline__ void mma16816(float* d, const uint32_t* a,
                                         uint32_t b0, uint32_t b1) {
    asm volatile("mma.sync.aligned.m16n8k16.row.col.f32.bf16.bf16.f32 "
                 "{%0,%1,%2,%3}, {%4,%5,%6,%7}, {%8,%9}, {%0,%1,%2,%3};"
                 : "+f"(d[0]), "+f"(d[1]), "+f"(d[2]), "+f"(d[3])
                 : "r"(a[0]), "r"(a[1]), "r"(a[2]), "r"(a[3]), "r"(b0), "r"(b1));
}

// fp16 variant (for P @ V)
__device__ __forceinline__ void mma16816h(float* d, const uint32_t* a,
                                          uint32_t b0, uint32_t b1) {
    asm volatile("mma.sync.aligned.m16n8k16.row.col.f32.f16.f16.f32 "
                 "{%0,%1,%2,%3}, {%4,%5,%6,%7}, {%8,%9}, {%0,%1,%2,%3};"
                 : "+f"(d[0]), "+f"(d[1]), "+f"(d[2]), "+f"(d[3])
                 : "r"(a[0]), "r"(a[1]), "r"(a[2]), "r"(a[3]), "r"(b0), "r"(b1));
}

// fast exp2
__device__ __forceinline__ float fexp2(float x) {
    float y;
    asm("ex2.approx.f32 %0, %1;" : "=f"(y) : "f"(x));
    return y;
}

// split two floats -> packed bf16x2 (hi) and bf16x2 (lo), 1-instr packing
__device__ __forceinline__ void split2(float a, float b, uint32_t& hi, uint32_t& lo) {
    asm("cvt.rn.bf16x2.f32 %0, %1, %2;" : "=r"(hi) : "f"(b), "f"(a));
    float ha = __uint_as_float(hi << 16);
    float hb = __uint_as_float(hi & 0xffff0000u);
    asm("cvt.rn.bf16x2.f32 %0, %1, %2;" : "=r"(lo) : "f"(b - hb), "f"(a - ha));
}

// pack two floats into fp16x2 bits
__device__ __forceinline__ uint32_t pack_h2(float a, float b) {
    __half2 h = __floats2half2_rn(a, b);
    return *(uint32_t*)&h;
}

// ---------------------------------------------------------------------------
// Merged split conversion, MLP=4: each thread loads 4 independent float4s.
// ---------------------------------------------------------------------------
#define CB_X   (NTOK*DMODEL/4096)           // 768
#define CB_W   (DMODEL*DMODEL/4096)         // 144
#define CB_F   (FFND*DMODEL/4096)           // 576
#define CB_TOTAL (CB_X + 4*CB_W + 2*CB_F)   // 2496

__global__ void __launch_bounds__(256) cvt_all_kernel(
    const float* __restrict__ x,
    const float* __restrict__ Wq, const float* __restrict__ Wk,
    const float* __restrict__ Wv, const float* __restrict__ Wo,
    const float* __restrict__ W1, const float* __restrict__ W2,
    bf16* __restrict__ xh,  bf16* __restrict__ xl,
    bf16* __restrict__ Wqh, bf16* __restrict__ Wql,
    bf16* __restrict__ Wkh, bf16* __restrict__ Wkl,
    bf16* __restrict__ Wvh, bf16* __restrict__ Wvl,
    bf16* __restrict__ Woh, bf16* __restrict__ Wol,
    bf16* __restrict__ W1h, bf16* __restrict__ W1l,
    bf16* __restrict__ W2h, bf16* __restrict__ W2l)
{
    int bi = blockIdx.x;
    const float* in; bf16 *hi, *lo; int base;
    if      (bi < CB_X)            { in = x;  hi = xh;  lo = xl;  base = 0; }
    else if (bi < CB_X + CB_W)     { in = Wq; hi = Wqh; lo = Wql; base = CB_X; }
    else if (bi < CB_X + 2*CB_W)   { in = Wk; hi = Wkh; lo = Wkl; base = CB_X + CB_W; }
    else if (bi < CB_X + 3*CB_W)   { in = Wv; hi = Wvh; lo = Wvl; base = CB_X + 2*CB_W; }
    else if (bi < CB_X + 4*CB_W)   { in = Wo; hi = Woh; lo = Wol; base = CB_X + 3*CB_W; }
    else if (bi < CB_X + 4*CB_W + CB_F)
                                   { in = W1; hi = W1h; lo = W1l; base = CB_X + 4*CB_W; }
    else                           { in = W2; hi = W2h; lo = W2l; base = CB_X + 4*CB_W + CB_F; }

    size_t e0 = (size_t)(bi - base) * 1024 + threadIdx.x;   // float4 index
    const float4* in4 = (const float4*)in;
    float4 v[4];
    #pragma unroll
    for (int j = 0; j < 4; j++) v[j] = in4[e0 + j * 256];   // 4 independent loads
    #pragma unroll
    for (int j = 0; j < 4; j++) {
        uint32_t h0, l0, h1, l1;
        split2(v[j].x, v[j].y, h0, l0);
        split2(v[j].z, v[j].w, h1, l1);
        size_t idx = (e0 + (size_t)j * 256) * 4;
        *(uint2*)(hi + idx) = make_uint2(h0, h1);
        *(uint2*)(lo + idx) = make_uint2(l0, l1);
    }
}

// ---------------------------------------------------------------------------
// Shared GEMM body (R8-measured structure): 128x128 tile, BK=32 (64B rows),
// 8 warps, 3-stage cp.async pipeline, 2 CTAs/SM. 3 MMA terms (hh, hl, lh).
// MODE 0: fp32 C + bias.  MODE 1: bf16 split out, (acc+bias)*scale.
// MODE 2: GELU -> bf16 split out.  MODE 5: single fp16 out (for V).
// ---------------------------------------------------------------------------
#define GSTAGE 32768                       // 4 matrices x 8KB
#define GSMEM_BYTES (3*GSTAGE + 1024)      // 99328 -> 2 CTA/SM

template<int MODE>
__device__ __forceinline__ void gemm_body(
    const bf16* __restrict__ Ah, const bf16* __restrict__ Al,
    const bf16* __restrict__ Bh, const bf16* __restrict__ Bl,
    const float* __restrict__ bias,
    float* __restrict__ C, bf16* __restrict__ Ch, bf16* __restrict__ Cl,
    int N, int ldk, int kIter, int k0, float scale, int m0, int n0)
{
    extern __shared__ __align__(1024) char smem_raw[];
    uint32_t sb = smem_u32(smem_raw);
    sb = (sb + 1023) & ~1023u;

    const int tid  = threadIdx.x;
    const int lane = tid & 31, wid = tid >> 5;
    const int wm = wid & 3, wn = wid >> 2;

    float acc[2][8][4];
    #pragma unroll
    for (int i = 0; i < 2; i++)
        #pragma unroll
        for (int j = 0; j < 8; j++)
            #pragma unroll
            for (int q = 0; q < 4; q++) acc[i][j][q] = 0.f;

    const int lrow = tid >> 1;
    const int c2   = (tid & 1) * 2;
    const bf16* pAh = Ah + (size_t)(m0 + lrow) * ldk + k0;
    const bf16* pAl = Al + (size_t)(m0 + lrow) * ldk + k0;
    const bf16* pBh = Bh + (size_t)(n0 + lrow) * ldk + k0;
    const bf16* pBl = Bl + (size_t)(n0 + lrow) * ldk + k0;
    const uint32_t swr = (uint32_t)((lrow >> 1) & 3);

    auto load_stage = [&](int s, int kt) {
        uint32_t st = sb + s * GSTAGE + lrow * 64;
        size_t ko = (size_t)kt * 32;
        #pragma unroll
        for (int cc = 0; cc < 2; cc++) {
            int c = c2 + cc;
            uint32_t off = (uint32_t)((c ^ swr) << 4);
            CP16(st + off,         pAh + ko + c * 8);
            CP16(st + 8192 + off,  pAl + ko + c * 8);
            CP16(st + 16384 + off, pBh + ko + c * 8);
            CP16(st + 24576 + off, pBl + ko + c * 8);
        }
    };

    const int nk = kIter >> 5;       // k32 tiles, always >= 4 here
    load_stage(0, 0); CP_COMMIT();
    load_stage(1, 1); CP_COMMIT();

    const int l15 = lane & 15, lh = lane >> 4;
    const int arowbase = wm * 32 + l15;
    const int browbase = wn * 64 + l15;
    int slot = 0, nslot = 2;

    for (int kt = 0; kt < nk; kt++) {
        if (kt + 1 < nk) CP_WAIT1(); else CP_WAIT0();
        __syncthreads();
        if (kt + 2 < nk) {
            load_stage(nslot, kt + 2);
            CP_COMMIT();
        }
        uint32_t st = sb + slot * GSTAGE;

        #pragma unroll
        for (int ks = 0; ks < 2; ks++) {
            const int chunk = ks * 2 + lh;
            uint32_t ah[2][4], al[2][4];
            #pragma unroll
            for (int mi = 0; mi < 2; mi++) {
                int row = arowbase + mi * 16;
                uint32_t ad = st + row * 64 + ((chunk ^ ((row >> 1) & 3)) << 4);
                ldsm4(ad,        ah[mi][0], ah[mi][1], ah[mi][2], ah[mi][3]);
                ldsm4(ad + 8192, al[mi][0], al[mi][1], al[mi][2], al[mi][3]);
            }
            uint32_t bh[2][4], bl[2][4];
            {
                uint32_t bd = st + 16384 + browbase * 64
                            + ((chunk ^ ((browbase >> 1) & 3)) << 4);
                ldsm4(bd,        bh[0][0], bh[0][1], bh[0][2], bh[0][3]);
                ldsm4(bd + 8192, bl[0][0], bl[0][1], bl[0][2], bl[0][3]);
            }
            #pragma unroll
            for (int g = 0; g < 4; g++) {
                const int cur = g & 1;
                if (g < 3) {
                    int row = browbase + (g + 1) * 16;
                    uint32_t bd = st + 16384 + row * 64
                                + ((chunk ^ ((row >> 1) & 3)) << 4);
                    ldsm4(bd,        bh[cur^1][0], bh[cur^1][1],
                                     bh[cur^1][2], bh[cur^1][3]);
                    ldsm4(bd + 8192, bl[cur^1][0], bl[cur^1][1],
                                     bl[cur^1][2], bl[cur^1][3]);
                }
                #pragma unroll
                for (int mi = 0; mi < 2; mi++) {
                    mma16816(acc[mi][2*g],   ah[mi], bh[cur][0], bh[cur][2]);
                    mma16816(acc[mi][2*g],   ah[mi], bl[cur][0], bl[cur][2]);
                    mma16816(acc[mi][2*g],   al[mi], bh[cur][0], bh[cur][2]);
                    mma16816(acc[mi][2*g+1], ah[mi], bh[cur][1], bh[cur][3]);
                    mma16816(acc[mi][2*g+1], ah[mi], bl[cur][1], bl[cur][3]);
                    mma16816(acc[mi][2*g+1], al[mi], bh[cur][1], bh[cur][3]);
                }
            }
        }
        slot = (slot == 2) ? 0 : slot + 1;
        nslot = (nslot == 2) ? 0 : nslot + 1;
    }

    const int g4 = lane >> 2, t4 = lane & 3;
    #pragma unroll
    for (int mi = 0; mi < 2; mi++) {
        #pragma unroll
        for (int n = 0; n < 8; n++) {
            int row = m0 + wm * 32 + mi * 16 + g4;
            int col = n0 + wn * 64 + n * 8 + t4 * 2;
            float b0 = bias[col], b1 = bias[col + 1];
            float v00 = acc[mi][n][0] + b0, v01 = acc[mi][n][1] + b1;
            float v10 = acc[mi][n][2] + b0, v11 = acc[mi][n][3] + b1;
            if (MODE == 0) {
                *(float2*)(C + (size_t)row * N + col)       = make_float2(v00, v01);
                *(float2*)(C + (size_t)(row + 8) * N + col) = make_float2(v10, v11);
            } else if (MODE == 5) {
                // single fp16 output (V path)
                *(uint32_t*)(Ch + (size_t)row * N + col)       = pack_h2(v00, v01);
                *(uint32_t*)(Ch + (size_t)(row + 8) * N + col) = pack_h2(v10, v11);
            } else {
                if (MODE == 1) {
                    v00 *= scale; v01 *= scale; v10 *= scale; v11 *= scale;
                } else {
                    v00 = 0.5f * v00 * (1.0f + erff(v00 * 0.70710678118654752f));
                    v01 = 0.5f * v01 * (1.0f + erff(v01 * 0.70710678118654752f));
                    v10 = 0.5f * v10 * (1.0f + erff(v10 * 0.70710678118654752f));
                    v11 = 0.5f * v11 * (1.0f + erff(v11 * 0.70710678118654752f));
                }
                uint32_t h0, l0, h1, l1;
                split2(v00, v01, h0, l0);
                split2(v10, v11, h1, l1);
                *(uint32_t*)(Ch + (size_t)row * N + col)       = h0;
                *(uint32_t*)(Ch + (size_t)(row + 8) * N + col) = h1;
                *(uint32_t*)(Cl + (size_t)row * N + col)       = l0;
                *(uint32_t*)(Cl + (size_t)(row + 8) * N + col) = l1;
            }
        }
    }
}

template<int MODE>
__global__ void __launch_bounds__(256, 2) gemm_mma(
    const bf16* __restrict__ Ah, const bf16* __restrict__ Al,
    const bf16* __restrict__ Bh, const bf16* __restrict__ Bl,
    const float* __restrict__ bias,
    float* __restrict__ C, bf16* __restrict__ Ch, bf16* __restrict__ Cl,
    int N, int K)
{
    gemm_body<MODE>(Ah, Al, Bh, Bl, bias, C, Ch, Cl, N, K, K, 0, 1.0f,
                    blockIdx.y * 128, blockIdx.x * 128);
}

// Split-K x3 (fp32 output): z=0 -> C0 (+bias), z=1 -> C1, z=2 -> C2.
__global__ void __launch_bounds__(256, 2) gemm_splitk(
    const bf16* __restrict__ Ah, const bf16* __restrict__ Al,
    const bf16* __restrict__ Bh, const bf16* __restrict__ Bl,
    const float* __restrict__ bias,
    float* __restrict__ C0, float* __restrict__ C1, float* __restrict__ C2,
    int N, int K)
{
    int z = blockIdx.z;
    int kh = K / 3;
    float* Cz = (z == 0) ? C0 : (z == 1) ? C1 : C2;
    gemm_body<0>(Ah, Al, Bh, Bl, z ? g_zero : bias, Cz,
                 nullptr, nullptr, N, K, kh, z * kh, 1.0f,
                 blockIdx.y * 128, blockIdx.x * 128);
}

// Combined QKV; Q pre-scaled by 0.125*log2(e); V emitted as single fp16.
#define QSCALE (0.125f * 1.4426950408889634f)
__global__ void __launch_bounds__(256, 2) gemm_qkv(
    const bf16* __restrict__ Ah, const bf16* __restrict__ Al,
    const bf16* __restrict__ Wqh, const bf16* __restrict__ Wql,
    const bf16* __restrict__ Wkh, const bf16* __restrict__ Wkl,
    const bf16* __restrict__ Wvh, const bf16* __restrict__ Wvl,
    const float* __restrict__ bq, const float* __restrict__ bk,
    const float* __restrict__ bv,
    bf16* __restrict__ qh, bf16* __restrict__ ql,
    bf16* __restrict__ kh, bf16* __restrict__ kl,
    bf16* __restrict__ vh)
{
    int z = blockIdx.z;
    if (z == 2) {
        gemm_body<5>(Ah, Al, Wvh, Wvl, bv, nullptr, vh, nullptr,
                     DMODEL, DMODEL, DMODEL, 0, 1.0f,
                     blockIdx.y * 128, blockIdx.x * 128);
    } else {
        const bf16* Bh = (z == 0) ? Wqh : Wkh;
        const bf16* Bl = (z == 0) ? Wql : Wkl;
        const float* bias = (z == 0) ? bq : bk;
        bf16* Ch = (z == 0) ? qh : kh;
        bf16* Cl = (z == 0) ? ql : kl;
        float scale = (z == 0) ? QSCALE : 1.0f;
        gemm_body<1>(Ah, Al, Bh, Bl, bias, nullptr, Ch, Cl,
                     DMODEL, DMODEL, DMODEL, 0, scale,
                     blockIdx.y * 128, blockIdx.x * 128);
    }
}

// ---------------------------------------------------------------------------
// Flash attention: Q-tile 128, key-tile 64, 2-stage KV, exp2 softmax.
// S = 3-term bf16 (near-exact). P@V = single fp16 x single fp16 -> 1 term,
// 32 MMAs/kt. KV stage = Kh 8K | Kl 8K | Vh 8K = 24KB.
// smem: Q 32K + 2x24K = 80.9KB -> 2 CTA/SM.
// ---------------------------------------------------------------------------
#define AKVSTAGE 24576
#define ASMEM_BYTES (32768 + 2*AKVSTAGE + 1024)

__global__ void __launch_bounds__(256, 2) attn_mma(
    const bf16* __restrict__ Qh, const bf16* __restrict__ Ql,
    const bf16* __restrict__ Kh, const bf16* __restrict__ Kl,
    const bf16* __restrict__ Vh,                               // fp16 bits
    bf16* __restrict__ Oh, bf16* __restrict__ Ol)
{
    extern __shared__ __align__(1024) char smem_raw[];
    uint32_t sb = smem_u32(smem_raw);
    sb = (sb + 1023) & ~1023u;

    const int tid  = threadIdx.x;
    const int lane = tid & 31, wq = tid >> 5;
    const int l15 = lane & 15, lh = lane >> 4;
    const int g4 = lane >> 2, t4 = lane & 3;
    const int b = blockIdx.z, h = blockIdx.y;
    const int q0 = blockIdx.x * 128;
    const size_t hoff = (size_t)h * HDIM;

    {
        int qrow = tid >> 1;
        int cb = (tid & 1) * 4;
        size_t gidx = ((size_t)(b * SEQ + q0 + qrow)) * DMODEL + hoff;
        uint32_t st = sb + qrow * 128;
        #pragma unroll
        for (int c = 0; c < 4; c++) {
            uint32_t ph = (uint32_t)(((cb + c) ^ (qrow & 7)) << 4);
            CP16(st + ph,         Qh + gidx + (cb + c) * 8);
            CP16(st + 16384 + ph, Ql + gidx + (cb + c) * 8);
        }
    }
    CP_COMMIT();

    const int krow = tid >> 2;
    const int kc0  = (tid & 3) * 2;
    auto load_kv = [&](int s, int kt) {
        uint32_t base = sb + 32768 + s * AKVSTAGE;
        size_t gidx = ((size_t)(b * SEQ + kt * 64 + krow)) * DMODEL + hoff;
        #pragma unroll
        for (int cc = 0; cc < 2; cc++) {
            int c = kc0 + cc;
            uint32_t off = krow * 128 + ((c ^ (krow & 7)) << 4);
            CP16(base + off,         Kh + gidx + c * 8);
            CP16(base + 8192 + off,  Kl + gidx + c * 8);
            CP16(base + 16384 + off, Vh + gidx + c * 8);
        }
    };
    load_kv(0, 0);
    CP_COMMIT();

    float m0 = -1e30f, m1 = -1e30f, l0 = 0.f, l1 = 0.f;
    float o[8][4];
    #pragma unroll
    for (int j = 0; j < 8; j++)
        #pragma unroll
        for (int q = 0; q < 4; q++) o[j][q] = 0.f;

    const int NT = SEQ / 64;
    for (int kt = 0; kt < NT; kt++) {
        CP_WAIT0();
        __syncthreads();
        if (kt + 1 < NT) {
            load_kv((kt + 1) & 1, kt + 1);
            CP_COMMIT();
        }

        uint32_t stb = sb + 32768 + (kt & 1) * AKVSTAGE;

        float s[8][4];
        #pragma unroll
        for (int j = 0; j < 8; j++)
            #pragma unroll
            for (int q = 0; q < 4; q++) s[j][q] = 0.f;

        #pragma unroll
        for (int kc = 0; kc < 4; kc++) {
            const int chunk = kc * 2 + lh;
            int arow = wq * 16 + l15;
            uint32_t aaddr = sb + arow * 128 + ((chunk ^ (arow & 7)) << 4);
            uint32_t qh_[4], ql_[4];
            ldsm4(aaddr,         qh_[0], qh_[1], qh_[2], qh_[3]);
            ldsm4(aaddr + 16384, ql_[0], ql_[1], ql_[2], ql_[3]);
            #pragma unroll
            for (int g = 0; g < 4; g++) {
                int brow = g * 16 + l15;
                uint32_t baddr = stb + brow * 128 + ((chunk ^ (brow & 7)) << 4);
                uint32_t kh_[4], kl_[4];
                ldsm4(baddr,        kh_[0], kh_[1], kh_[2], kh_[3]);
                ldsm4(baddr + 8192, kl_[0], kl_[1], kl_[2], kl_[3]);
                mma16816(s[2*g],   qh_, kh_[0], kh_[2]);
                mma16816(s[2*g],   qh_, kl_[0], kl_[2]);
                mma16816(s[2*g],   ql_, kh_[0], kh_[2]);
                mma16816(s[2*g+1], qh_, kh_[1], kh_[3]);
                mma16816(s[2*g+1], qh_, kl_[1], kl_[3]);
                mma16816(s[2*g+1], ql_, kh_[1], kh_[3]);
            }
        }

        float mx0 = -1e30f, mx1 = -1e30f;
        #pragma unroll
        for (int j = 0; j < 8; j++) {
            mx0 = fmaxf(mx0, fmaxf(s[j][0], s[j][1]));
            mx1 = fmaxf(mx1, fmaxf(s[j][2], s[j][3]));
        }
        mx0 = fmaxf(mx0, __shfl_xor_sync(0xffffffffu, mx0, 1));
        mx0 = fmaxf(mx0, __shfl_xor_sync(0xffffffffu, mx0, 2));
        mx1 = fmaxf(mx1, __shfl_xor_sync(0xffffffffu, mx1, 1));
        mx1 = fmaxf(mx1, __shfl_xor_sync(0xffffffffu, mx1, 2));

        float mn0 = fmaxf(m0, mx0), mn1 = fmaxf(m1, mx1);
        float a0 = fexp2(m0 - mn0), a1 = fexp2(m1 - mn1);
        m0 = mn0; m1 = mn1;

        float sum0 = 0.f, sum1 = 0.f;
        #pragma unroll
        for (int j = 0; j < 8; j++) {
            s[j][0] = fexp2(s[j][0] - mn0);
            s[j][1] = fexp2(s[j][1] - mn0);
            s[j][2] = fexp2(s[j][2] - mn1);
            s[j][3] = fexp2(s[j][3] - mn1);
            sum0 += s[j][0] + s[j][1];
            sum1 += s[j][2] + s[j][3];
        }
        sum0 += __shfl_xor_sync(0xffffffffu, sum0, 1);
        sum0 += __shfl_xor_sync(0xffffffffu, sum0, 2);
        sum1 += __shfl_xor_sync(0xffffffffu, sum1, 1);
        sum1 += __shfl_xor_sync(0xffffffffu, sum1, 2);
        l0 = l0 * a0 + sum0;
        l1 = l1 * a1 + sum1;

        #pragma unroll
        for (int j = 0; j < 8; j++) {
            o[j][0] *= a0; o[j][1] *= a0;
            o[j][2] *= a1; o[j][3] *= a1;
        }

        // ---- O += P @ V: single-fp16 P x single-fp16 V (1 term) ----
        #pragma unroll
        for (int kc = 0; kc < 4; kc++) {
            uint32_t ph_[4];
            ph_[0] = pack_h2(s[2*kc][0],   s[2*kc][1]);
            ph_[1] = pack_h2(s[2*kc][2],   s[2*kc][3]);
            ph_[2] = pack_h2(s[2*kc+1][0], s[2*kc+1][1]);
            ph_[3] = pack_h2(s[2*kc+1][2], s[2*kc+1][3]);

            int vrow = kc * 16 + (lane & 7) + ((lane >> 3) & 1) * 8;
            #pragma unroll
            for (int nn = 0; nn < 4; nn++) {
                int colchunk = nn * 2 + (lane >> 4);
                uint32_t vaddr = stb + 16384 + vrow * 128
                               + ((colchunk ^ (vrow & 7)) << 4);
                uint32_t vh_[4];
                ldsm4t(vaddr, vh_[0], vh_[1], vh_[2], vh_[3]);
                mma16816h(o[2*nn],   ph_, vh_[0], vh_[1]);
                mma16816h(o[2*nn+1], ph_, vh_[2], vh_[3]);
            }
        }
    }

    float i0 = 1.0f / l0, i1 = 1.0f / l1;
    int row0 = b * SEQ + q0 + wq * 16 + g4;
    #pragma unroll
    for (int j = 0; j < 8; j++) {
        int col = (int)hoff + j * 8 + t4 * 2;
        uint32_t h0, lo0, h1, lo1;
        split2(o[j][0] * i0, o[j][1] * i0, h0, lo0);
        split2(o[j][2] * i1, o[j][3] * i1, h1, lo1);
        *(uint32_t*)(Oh + (size_t)row0 * DMODEL + col)       = h0;
        *(uint32_t*)(Ol + (size_t)row0 * DMODEL + col)       = lo0;
        *(uint32_t*)(Oh + (size_t)(row0 + 8) * DMODEL + col) = h1;
        *(uint32_t*)(Ol + (size_t)(row0 + 8) * DMODEL + col) = lo1;
    }
}

// ---------------------------------------------------------------------------
// Fused residual add + LayerNorm over (y0 + y1 + y2 + residual).
// ---------------------------------------------------------------------------
__global__ void __launch_bounds__(256) ln_res_kernel(
    const float* __restrict__ y0, const float* __restrict__ y1,
    const float* __restrict__ y2, const float* __restrict__ r,
    const float* __restrict__ g, const float* __restrict__ b,
    float* __restrict__ o, bf16* __restrict__ oh, bf16* __restrict__ ol)
{
    const int row = blockIdx.x;
    const int tid = threadIdx.x;
    const float* y0p = y0 + (size_t)row * DMODEL;
    const float* y1p = y1 + (size_t)row * DMODEL;
    const float* y2p = y2 + (size_t)row * DMODEL;
    const float* rp  = r  + (size_t)row * DMODEL;

    float v[3];
    float s = 0.f, ss = 0.f;
    #pragma unroll
    for (int j = 0; j < 3; j++) {
        int c = tid + j * 256;
        float a = y0p[c] + y1p[c] + y2p[c] + rp[c];
        v[j] = a; s += a; ss += a * a;
    }
    #pragma unroll
    for (int off = 16; off; off >>= 1) {
        s  += __shfl_xor_sync(0xffffffffu, s, off);
        ss += __shfl_xor_sync(0xffffffffu, ss, off);
    }
    __shared__ float sred[16];
    if ((tid & 31) == 0) { sred[tid >> 5] = s; sred[8 + (tid >> 5)] = ss; }
    __syncthreads();
    if (tid == 0) {
        float S = 0.f, SS = 0.f;
        #pragma unroll
        for (int w = 0; w < 8; w++) { S += sred[w]; SS += sred[8 + w]; }
        sred[0] = S * (1.0f / DMODEL);
        sred[1] = SS * (1.0f / DMODEL);
    }
    __syncthreads();
    float mu  = sred[0];
    float var = sred[1] - mu * mu;
    float rstd = rsqrtf(var + 1e-5f);
    float* op = o + (size_t)row * DMODEL;
    #pragma unroll
    for (int j = 0; j < 3; j++) {
        int c = tid + j * 256;
        float val = (v[j] - mu) * rstd * g[c] + b[c];
        op[c] = val;
        if (oh) {
            bf16 hv = __float2bfloat16(val);
            oh[(size_t)row * DMODEL + c] = hv;
            ol[(size_t)row * DMODEL + c] =
                __float2bfloat16(val - __bfloat162float(hv));
        }
    }
}

// ---------------------------------------------------------------------------
extern "C" void kernel_launch(void* const* d_in, const int* in_sizes, int n_in,
                              void* d_out, int out_size)
{
    const float* x     = (const float*)d_in[0];
    const float* Wq    = (const float*)d_in[1];
    const float* bq    = (const float*)d_in[2];
    const float* Wk    = (const float*)d_in[3];
    const float* bk    = (const float*)d_in[4];
    const float* Wv    = (const float*)d_in[5];
    const float* bv    = (const float*)d_in[6];
    const float* Wo    = (const float*)d_in[7];
    const float* bo    = (const float*)d_in[8];
    const float* ln1g  = (const float*)d_in[9];
    const float* ln1b  = (const float*)d_in[10];
    const float* ln2g  = (const float*)d_in[11];
    const float* ln2b  = (const float*)d_in[12];
    const float* W1    = (const float*)d_in[13];
    const float* b1    = (const float*)d_in[14];
    const float* W2    = (const float*)d_in[15];
    const float* b2    = (const float*)d_in[16];
    float* out = (float*)d_out;

    float *p, *p2, *p3, *x1, *f, *f2, *f3;
    cudaGetSymbolAddress((void**)&p,  g_p);
    cudaGetSymbolAddress((void**)&p2, g_p2);
    cudaGetSymbolAddress((void**)&p3, g_p3);
    cudaGetSymbolAddress((void**)&x1, g_x1);
    cudaGetSymbolAddress((void**)&f,  g_f);
    cudaGetSymbolAddress((void**)&f2, g_f2);
    cudaGetSymbolAddress((void**)&f3, g_f3);

    bf16 *xh,*xl,*qh,*ql,*kh,*kl,*vh,*ah,*al,*x1h,*x1l,*hh,*hl;
    bf16 *Wqh,*Wql,*Wkh,*Wkl,*Wvh,*Wvl,*Woh,*Wol,*W1h,*W1l,*W2h,*W2l;
    cudaGetSymbolAddress((void**)&xh,  g_xh);  cudaGetSymbolAddress((void**)&xl,  g_xl);
    cudaGetSymbolAddress((void**)&qh,  g_qh);  cudaGetSymbolAddress((void**)&ql,  g_ql);
    cudaGetSymbolAddress((void**)&kh,  g_kh);  cudaGetSymbolAddress((void**)&kl,  g_kl);
    cudaGetSymbolAddress((void**)&vh,  g_vh);
    cudaGetSymbolAddress((void**)&ah,  g_ah);  cudaGetSymbolAddress((void**)&al,  g_al);
    cudaGetSymbolAddress((void**)&x1h, g_x1h); cudaGetSymbolAddress((void**)&x1l, g_x1l);
    cudaGetSymbolAddress((void**)&hh,  g_hh);  cudaGetSymbolAddress((void**)&hl,  g_hl);
    cudaGetSymbolAddress((void**)&Wqh, g_Wqh); cudaGetSymbolAddress((void**)&Wql, g_Wql);
    cudaGetSymbolAddress((void**)&Wkh, g_Wkh); cudaGetSymbolAddress((void**)&Wkl, g_Wkl);
    cudaGetSymbolAddress((void**)&Wvh, g_Wvh); cudaGetSymbolAddress((void**)&Wvl, g_Wvl);
    cudaGetSymbolAddress((void**)&Woh, g_Woh); cudaGetSymbolAddress((void**)&Wol, g_Wol);
    cudaGetSymbolAddress((void**)&W1h, g_W1h); cudaGetSymbolAddress((void**)&W1l, g_W1l);
    cudaGetSymbolAddress((void**)&W2h, g_W2h); cudaGetSymbolAddress((void**)&W2l, g_W2l);

    cudaFuncSetAttribute(gemm_mma<2>,
                         cudaFuncAttributeMaxDynamicSharedMemorySize, GSMEM_BYTES);
    cudaFuncSetAttribute(gemm_splitk,
                         cudaFuncAttributeMaxDynamicSharedMemorySize, GSMEM_BYTES);
    cudaFuncSetAttribute(gemm_qkv,
                         cudaFuncAttributeMaxDynamicSharedMemorySize, GSMEM_BYTES);
    cudaFuncSetAttribute(attn_mma,
                         cudaFuncAttributeMaxDynamicSharedMemorySize, ASMEM_BYTES);

    dim3 blk(256);

    // Merged split conversion, MLP=4
    cvt_all_kernel<<<CB_TOTAL, blk>>>(x, Wq, Wk, Wv, Wo, W1, W2,
                                      xh, xl, Wqh, Wql, Wkh, Wkl, Wvh, Wvl,
                                      Woh, Wol, W1h, W1l, W2h, W2l);

    // QKV combined (Q/K bf16 split, V single fp16; Q pre-scaled)
    dim3 gqkv(DMODEL / 128, NTOK / 128, 3);
    gemm_qkv<<<gqkv, blk, GSMEM_BYTES>>>(xh, xl, Wqh, Wql, Wkh, Wkl, Wvh, Wvl,
                                         bq, bk, bv, qh, ql, kh, kl, vh);

    // Attention (exp2-domain; single-term fp16 P@V)
    dim3 ga(SEQ / 128, NHEAD, BATCH);
    attn_mma<<<ga, blk, ASMEM_BYTES>>>(qh, ql, kh, kl, vh, ah, al);

    // Output projection (split-K x3) + residual LN1
    dim3 gS(DMODEL / 128, NTOK / 128, 3);
    gemm_splitk<<<gS, blk, GSMEM_BYTES>>>(ah, al, Woh, Wol, bo, p, p2, p3,
                                          DMODEL, DMODEL);
    ln_res_kernel<<<NTOK, blk>>>(p, p2, p3, x, ln1g, ln1b, x1, x1h, x1l);

    // FFN1 (GELU, bf16 split hidden)
    dim3 gF(FFND / 128, NTOK / 128);
    gemm_mma<2><<<gF, blk, GSMEM_BYTES>>>(x1h, x1l, W1h, W1l, b1,
                                          nullptr, hh, hl, FFND, DMODEL);
    // FFN2 (split-K x3) + residual LN2 -> out
    gemm_splitk<<<gS, blk, GSMEM_BYTES>>>(hh, hl, W2h, W2l, b2, f, f2, f3,
                                          DMODEL, FFND);
    ln_res_kernel<<<NTOK, blk>>>(f, f2, f3, x1, ln2g, ln2b, out, nullptr, nullptr);
}

// round 17
// speedup vs baseline: 1.1856x; 1.0855x over previous
#include <cuda_runtime.h>
#include <cuda_bf16.h>
#include <cuda_fp16.h>
#include <math.h>
#include <stdint.h>

// Problem constants
#define DMODEL 768
#define FFND   3072
#define SEQ    2048
#define BATCH  2
#define NTOK   4096
#define NHEAD  12
#define HDIM   64

typedef __nv_bfloat16 bf16;

// ---------------------------------------------------------------------------
// Scratch (__device__ globals; no allocations allowed)
// ---------------------------------------------------------------------------
__device__ float g_p [NTOK * DMODEL];
__device__ float g_p2[NTOK * DMODEL];
__device__ float g_p3[NTOK * DMODEL];
__device__ float g_x1[NTOK * DMODEL];
__device__ float g_f [NTOK * DMODEL];
__device__ float g_f2[NTOK * DMODEL];
__device__ float g_f3[NTOK * DMODEL];
__device__ float g_zero[DMODEL];          // zero-initialized, never written

__device__ bf16 g_xh [NTOK * DMODEL], g_xl [NTOK * DMODEL];
__device__ bf16 g_qh [NTOK * DMODEL];                        // fp16 bits
__device__ bf16 g_kh [NTOK * DMODEL];                        // fp16 bits
__device__ bf16 g_vh [NTOK * DMODEL];                        // fp16 bits
__device__ bf16 g_ah [NTOK * DMODEL], g_al [NTOK * DMODEL];
__device__ bf16 g_x1h[NTOK * DMODEL], g_x1l[NTOK * DMODEL];
__device__ bf16 g_hh [NTOK * FFND],   g_hl [NTOK * FFND];
__device__ bf16 g_Wqh[DMODEL*DMODEL], g_Wql[DMODEL*DMODEL];
__device__ bf16 g_Wkh[DMODEL*DMODEL], g_Wkl[DMODEL*DMODEL];
__device__ bf16 g_Wvh[DMODEL*DMODEL], g_Wvl[DMODEL*DMODEL];
__device__ bf16 g_Woh[DMODEL*DMODEL], g_Wol[DMODEL*DMODEL];
__device__ bf16 g_W1h[FFND*DMODEL],   g_W1l[FFND*DMODEL];
__device__ bf16 g_W2h[DMODEL*FFND],   g_W2l[DMODEL*FFND];

// ---------------------------------------------------------------------------
// PTX helpers (sm_103 base target safe)
// ---------------------------------------------------------------------------
__device__ __forceinline__ uint32_t smem_u32(const void* p) {
    uint32_t a;
    asm("{ .reg .u64 t; cvta.to.shared.u64 t, %1; cvt.u32.u64 %0, t; }"
        : "=r"(a) : "l"(p));
    return a;
}

#define CP16(dst, src) \
    asm volatile("cp.async.cg.shared.global [%0], [%1], 16;" :: "r"(dst), "l"(src))
#define CP_COMMIT() asm volatile("cp.async.commit_group;" ::: "memory")
#define CP_WAIT0()  asm volatile("cp.async.wait_group 0;" ::: "memory")
#define CP_WAIT1()  asm volatile("cp.async.wait_group 1;" ::: "memory")

__device__ __forceinline__ void ldsm4(uint32_t a, uint32_t& r0, uint32_t& r1,
                                      uint32_t& r2, uint32_t& r3) {
    asm volatile("ldmatrix.sync.aligned.m8n8.x4.shared.b16 {%0,%1,%2,%3}, [%4];"
                 : "=r"(r0), "=r"(r1), "=r"(r2), "=r"(r3) : "r"(a));
}
__device__ __forceinline__ void ldsm4t(uint32_t a, uint32_t& r0, uint32_t& r1,
                                       uint32_t& r2, uint32_t& r3) {
    asm volatile("ldmatrix.sync.aligned.m8n8.x4.trans.shared.b16 {%0,%1,%2,%3}, [%4];"
                 : "=r"(r0), "=r"(r1), "=r"(r2), "=r"(r3) : "r"(a));
}

__device__ __forceinline__ void mma16816(float* d, const uint32_t* a,
                                         uint32_t b0, uint32_t b1) {
    asm volatile("mma.sync.aligned.m16n8k16.row.col.f32.bf16.bf16.f32 "
                 "{%0,%1,%2,%3}, {%4,%5,%6,%7}, {%8,%9}, {%0,%1,%2,%3};"
                 : "+f"(d[0]), "+f"(d[1]), "+f"(d[2]), "+f"(d[3])
                 : "r"(a[0]), "r"(a[1]), "r"(a[2]), "r"(a[3]), "r"(b0), "r"(b1));
}

// fp16 variant (attention)
__device__ __forceinline__ void mma16816h(float* d, const uint32_t* a,
                                          uint32_t b0, uint32_t b1) {
    asm volatile("mma.sync.aligned.m16n8k16.row.col.f32.f16.f16.f32 "
                 "{%0,%1,%2,%3}, {%4,%5,%6,%7}, {%8,%9}, {%0,%1,%2,%3};"
                 : "+f"(d[0]), "+f"(d[1]), "+f"(d[2]), "+f"(d[3])
                 : "r"(a[0]), "r"(a[1]), "r"(a[2]), "r"(a[3]), "r"(b0), "r"(b1));
}

// fast exp2
__device__ __forceinline__ float fexp2(float x) {
    float y;
    asm("ex2.approx.f32 %0, %1;" : "=f"(y) : "f"(x));
    return y;
}

// split two floats -> packed bf16x2 (hi) and bf16x2 (lo), 1-instr packing
__device__ __forceinline__ void split2(float a, float b, uint32_t& hi, uint32_t& lo) {
    asm("cvt.rn.bf16x2.f32 %0, %1, %2;" : "=r"(hi) : "f"(b), "f"(a));
    float ha = __uint_as_float(hi << 16);
    float hb = __uint_as_float(hi & 0xffff0000u);
    asm("cvt.rn.bf16x2.f32 %0, %1, %2;" : "=r"(lo) : "f"(b - hb), "f"(a - ha));
}

// pack two floats into fp16x2 bits
__device__ __forceinline__ uint32_t pack_h2(float a, float b) {
    __half2 h = __floats2half2_rn(a, b);
    return *(uint32_t*)&h;
}

// ---------------------------------------------------------------------------
// Merged split conversion, MLP=4: each thread loads 4 independent float4s.
// ---------------------------------------------------------------------------
#define CB_X   (NTOK*DMODEL/4096)           // 768
#define CB_W   (DMODEL*DMODEL/4096)         // 144
#define CB_F   (FFND*DMODEL/4096)           // 576
#define CB_TOTAL (CB_X + 4*CB_W + 2*CB_F)   // 2496

__global__ void __launch_bounds__(256) cvt_all_kernel(
    const float* __restrict__ x,
    const float* __restrict__ Wq, const float* __restrict__ Wk,
    const float* __restrict__ Wv, const float* __restrict__ Wo,
    const float* __restrict__ W1, const float* __restrict__ W2,
    bf16* __restrict__ xh,  bf16* __restrict__ xl,
    bf16* __restrict__ Wqh, bf16* __restrict__ Wql,
    bf16* __restrict__ Wkh, bf16* __restrict__ Wkl,
    bf16* __restrict__ Wvh, bf16* __restrict__ Wvl,
    bf16* __restrict__ Woh, bf16* __restrict__ Wol,
    bf16* __restrict__ W1h, bf16* __restrict__ W1l,
    bf16* __restrict__ W2h, bf16* __restrict__ W2l)
{
    int bi = blockIdx.x;
    const float* in; bf16 *hi, *lo; int base;
    if      (bi < CB_X)            { in = x;  hi = xh;  lo = xl;  base = 0; }
    else if (bi < CB_X + CB_W)     { in = Wq; hi = Wqh; lo = Wql; base = CB_X; }
    else if (bi < CB_X + 2*CB_W)   { in = Wk; hi = Wkh; lo = Wkl; base = CB_X + CB_W; }
    else if (bi < CB_X + 3*CB_W)   { in = Wv; hi = Wvh; lo = Wvl; base = CB_X + 2*CB_W; }
    else if (bi < CB_X + 4*CB_W)   { in = Wo; hi = Woh; lo = Wol; base = CB_X + 3*CB_W; }
    else if (bi < CB_X + 4*CB_W + CB_F)
                                   { in = W1; hi = W1h; lo = W1l; base = CB_X + 4*CB_W; }
    else                           { in = W2; hi = W2h; lo = W2l; base = CB_X + 4*CB_W + CB_F; }

    size_t e0 = (size_t)(bi - base) * 1024 + threadIdx.x;   // float4 index
    const float4* in4 = (const float4*)in;
    float4 v[4];
    #pragma unroll
    for (int j = 0; j < 4; j++) v[j] = in4[e0 + j * 256];   // 4 independent loads
    #pragma unroll
    for (int j = 0; j < 4; j++) {
        uint32_t h0, l0, h1, l1;
        split2(v[j].x, v[j].y, h0, l0);
        split2(v[j].z, v[j].w, h1, l1);
        size_t idx = (e0 + (size_t)j * 256) * 4;
        *(uint2*)(hi + idx) = make_uint2(h0, h1);
        *(uint2*)(lo + idx) = make_uint2(l0, l1);
    }
}

// ---------------------------------------------------------------------------
// Shared GEMM body (R8-measured structure): 128x128 tile, BK=32 (64B rows),
// 8 warps, 3-stage cp.async pipeline, 2 CTAs/SM. 3 MMA terms (hh, hl, lh).
// MODE 0: fp32 C + bias.  MODE 1: bf16 split out, (acc+bias)*scale.
// MODE 2: GELU -> bf16 split out.  MODE 5: single fp16 out, (acc+bias)*scale.
// ---------------------------------------------------------------------------
#define GSTAGE 32768                       // 4 matrices x 8KB
#define GSMEM_BYTES (3*GSTAGE + 1024)      // 99328 -> 2 CTA/SM

template<int MODE>
__device__ __forceinline__ void gemm_body(
    const bf16* __restrict__ Ah, const bf16* __restrict__ Al,
    const bf16* __restrict__ Bh, const bf16* __restrict__ Bl,
    const float* __restrict__ bias,
    float* __restrict__ C, bf16* __restrict__ Ch, bf16* __restrict__ Cl,
    int N, int ldk, int kIter, int k0, float scale, int m0, int n0)
{
    extern __shared__ __align__(1024) char smem_raw[];
    uint32_t sb = smem_u32(smem_raw);
    sb = (sb + 1023) & ~1023u;

    const int tid  = threadIdx.x;
    const int lane = tid & 31, wid = tid >> 5;
    const int wm = wid & 3, wn = wid >> 2;

    float acc[2][8][4];
    #pragma unroll
    for (int i = 0; i < 2; i++)
        #pragma unroll
        for (int j = 0; j < 8; j++)
            #pragma unroll
            for (int q = 0; q < 4; q++) acc[i][j][q] = 0.f;

    const int lrow = tid >> 1;
    const int c2   = (tid & 1) * 2;
    const bf16* pAh = Ah + (size_t)(m0 + lrow) * ldk + k0;
    const bf16* pAl = Al + (size_t)(m0 + lrow) * ldk + k0;
    const bf16* pBh = Bh + (size_t)(n0 + lrow) * ldk + k0;
    const bf16* pBl = Bl + (size_t)(n0 + lrow) * ldk + k0;
    const uint32_t swr = (uint32_t)((lrow >> 1) & 3);

    auto load_stage = [&](int s, int kt) {
        uint32_t st = sb + s * GSTAGE + lrow * 64;
        size_t ko = (size_t)kt * 32;
        #pragma unroll
        for (int cc = 0; cc < 2; cc++) {
            int c = c2 + cc;
            uint32_t off = (uint32_t)((c ^ swr) << 4);
            CP16(st + off,         pAh + ko + c * 8);
            CP16(st + 8192 + off,  pAl + ko + c * 8);
            CP16(st + 16384 + off, pBh + ko + c * 8);
            CP16(st + 24576 + off, pBl + ko + c * 8);
        }
    };

    const int nk = kIter >> 5;       // k32 tiles, always >= 4 here
    load_stage(0, 0); CP_COMMIT();
    load_stage(1, 1); CP_COMMIT();

    const int l15 = lane & 15, lh = lane >> 4;
    const int arowbase = wm * 32 + l15;
    const int browbase = wn * 64 + l15;
    int slot = 0, nslot = 2;

    for (int kt = 0; kt < nk; kt++) {
        if (kt + 1 < nk) CP_WAIT1(); else CP_WAIT0();
        __syncthreads();
        if (kt + 2 < nk) {
            load_stage(nslot, kt + 2);
            CP_COMMIT();
        }
        uint32_t st = sb + slot * GSTAGE;

        #pragma unroll
        for (int ks = 0; ks < 2; ks++) {
            const int chunk = ks * 2 + lh;
            uint32_t ah[2][4], al[2][4];
            #pragma unroll
            for (int mi = 0; mi < 2; mi++) {
                int row = arowbase + mi * 16;
                uint32_t ad = st + row * 64 + ((chunk ^ ((row >> 1) & 3)) << 4);
                ldsm4(ad,        ah[mi][0], ah[mi][1], ah[mi][2], ah[mi][3]);
                ldsm4(ad + 8192, al[mi][0], al[mi][1], al[mi][2], al[mi][3]);
            }
            uint32_t bh[2][4], bl[2][4];
            {
                uint32_t bd = st + 16384 + browbase * 64
                            + ((chunk ^ ((browbase >> 1) & 3)) << 4);
                ldsm4(bd,        bh[0][0], bh[0][1], bh[0][2], bh[0][3]);
                ldsm4(bd + 8192, bl[0][0], bl[0][1], bl[0][2], bl[0][3]);
            }
            #pragma unroll
            for (int g = 0; g < 4; g++) {
                const int cur = g & 1;
                if (g < 3) {
                    int row = browbase + (g + 1) * 16;
                    uint32_t bd = st + 16384 + row * 64
                                + ((chunk ^ ((row >> 1) & 3)) << 4);
                    ldsm4(bd,        bh[cur^1][0], bh[cur^1][1],
                                     bh[cur^1][2], bh[cur^1][3]);
                    ldsm4(bd + 8192, bl[cur^1][0], bl[cur^1][1],
                                     bl[cur^1][2], bl[cur^1][3]);
                }
                #pragma unroll
                for (int mi = 0; mi < 2; mi++) {
                    mma16816(acc[mi][2*g],   ah[mi], bh[cur][0], bh[cur][2]);
                    mma16816(acc[mi][2*g],   ah[mi], bl[cur][0], bl[cur][2]);
                    mma16816(acc[mi][2*g],   al[mi], bh[cur][0], bh[cur][2]);
                    mma16816(acc[mi][2*g+1], ah[mi], bh[cur][1], bh[cur][3]);
                    mma16816(acc[mi][2*g+1], ah[mi], bl[cur][1], bl[cur][3]);
                    mma16816(acc[mi][2*g+1], al[mi], bh[cur][1], bh[cur][3]);
                }
            }
        }
        slot = (slot == 2) ? 0 : slot + 1;
        nslot = (nslot == 2) ? 0 : nslot + 1;
    }

    const int g4 = lane >> 2, t4 = lane & 3;
    #pragma unroll
    for (int mi = 0; mi < 2; mi++) {
        #pragma unroll
        for (int n = 0; n < 8; n++) {
            int row = m0 + wm * 32 + mi * 16 + g4;
            int col = n0 + wn * 64 + n * 8 + t4 * 2;
            float b0 = bias[col], b1 = bias[col + 1];
            float v00 = acc[mi][n][0] + b0, v01 = acc[mi][n][1] + b1;
            float v10 = acc[mi][n][2] + b0, v11 = acc[mi][n][3] + b1;
            if (MODE == 0) {
                *(float2*)(C + (size_t)row * N + col)       = make_float2(v00, v01);
                *(float2*)(C + (size_t)(row + 8) * N + col) = make_float2(v10, v11);
            } else if (MODE == 5) {
                // single fp16 output, scaled (Q/K/V path)
                v00 *= scale; v01 *= scale; v10 *= scale; v11 *= scale;
                *(uint32_t*)(Ch + (size_t)row * N + col)       = pack_h2(v00, v01);
                *(uint32_t*)(Ch + (size_t)(row + 8) * N + col) = pack_h2(v10, v11);
            } else {
                if (MODE == 1) {
                    v00 *= scale; v01 *= scale; v10 *= scale; v11 *= scale;
                } else {
                    v00 = 0.5f * v00 * (1.0f + erff(v00 * 0.70710678118654752f));
                    v01 = 0.5f * v01 * (1.0f + erff(v01 * 0.70710678118654752f));
                    v10 = 0.5f * v10 * (1.0f + erff(v10 * 0.70710678118654752f));
                    v11 = 0.5f * v11 * (1.0f + erff(v11 * 0.70710678118654752f));
                }
                uint32_t h0, l0, h1, l1;
                split2(v00, v01, h0, l0);
                split2(v10, v11, h1, l1);
                *(uint32_t*)(Ch + (size_t)row * N + col)       = h0;
                *(uint32_t*)(Ch + (size_t)(row + 8) * N + col) = h1;
                *(uint32_t*)(Cl + (size_t)row * N + col)       = l0;
                *(uint32_t*)(Cl + (size_t)(row + 8) * N + col) = l1;
            }
        }
    }
}

template<int MODE>
__global__ void __launch_bounds__(256, 2) gemm_mma(
    const bf16* __restrict__ Ah, const bf16* __restrict__ Al,
    const bf16* __restrict__ Bh, const bf16* __restrict__ Bl,
    const float* __restrict__ bias,
    float* __restrict__ C, bf16* __restrict__ Ch, bf16* __restrict__ Cl,
    int N, int K)
{
    gemm_body<MODE>(Ah, Al, Bh, Bl, bias, C, Ch, Cl, N, K, K, 0, 1.0f,
                    blockIdx.y * 128, blockIdx.x * 128);
}

// Split-K x3 (fp32 output): z=0 -> C0 (+bias), z=1 -> C1, z=2 -> C2.
__global__ void __launch_bounds__(256, 2) gemm_splitk(
    const bf16* __restrict__ Ah, const bf16* __restrict__ Al,
    const bf16* __restrict__ Bh, const bf16* __restrict__ Bl,
    const float* __restrict__ bias,
    float* __restrict__ C0, float* __restrict__ C1, float* __restrict__ C2,
    int N, int K)
{
    int z = blockIdx.z;
    int kh = K / 3;
    float* Cz = (z == 0) ? C0 : (z == 1) ? C1 : C2;
    gemm_body<0>(Ah, Al, Bh, Bl, z ? g_zero : bias, Cz,
                 nullptr, nullptr, N, K, kh, z * kh, 1.0f,
                 blockIdx.y * 128, blockIdx.x * 128);
}

// Combined QKV; all outputs single fp16. Q pre-scaled by 0.125*log2(e).
#define QSCALE (0.125f * 1.4426950408889634f)
__global__ void __launch_bounds__(256, 2) gemm_qkv(
    const bf16* __restrict__ Ah, const bf16* __restrict__ Al,
    const bf16* __restrict__ Wqh, const bf16* __restrict__ Wql,
    const bf16* __restrict__ Wkh, const bf16* __restrict__ Wkl,
    const bf16* __restrict__ Wvh, const bf16* __restrict__ Wvl,
    const float* __restrict__ bq, const float* __restrict__ bk,
    const float* __restrict__ bv,
    bf16* __restrict__ qh, bf16* __restrict__ kh, bf16* __restrict__ vh)
{
    int z = blockIdx.z;
    const bf16* Bh = (z == 0) ? Wqh : (z == 1) ? Wkh : Wvh;
    const bf16* Bl = (z == 0) ? Wql : (z == 1) ? Wkl : Wvl;
    const float* bias = (z == 0) ? bq : (z == 1) ? bk : bv;
    bf16* Ch = (z == 0) ? qh : (z == 1) ? kh : vh;
    float scale = (z == 0) ? QSCALE : 1.0f;
    gemm_body<5>(Ah, Al, Bh, Bl, bias, nullptr, Ch, nullptr,
                 DMODEL, DMODEL, DMODEL, 0, scale,
                 blockIdx.y * 128, blockIdx.x * 128);
}

// ---------------------------------------------------------------------------
// Flash attention, all-fp16 single-term: Q-tile 128, key-tile 64, 2-stage KV,
// exp2 softmax. S: 32 MMAs/kt, P@V: 32 MMAs/kt.
// smem: Q 16K + 2 x (Kh 8K | Vh 8K) = 49 KB -> 2 CTA/SM.
// ---------------------------------------------------------------------------
#define AKVSTAGE 16384
#define ASMEM_BYTES (16384 + 2*AKVSTAGE + 1024)

__global__ void __launch_bounds__(256, 2) attn_mma(
    const bf16* __restrict__ Qh, const bf16* __restrict__ Kh,
    const bf16* __restrict__ Vh,                               // all fp16 bits
    bf16* __restrict__ Oh, bf16* __restrict__ Ol)
{
    extern __shared__ __align__(1024) char smem_raw[];
    uint32_t sb = smem_u32(smem_raw);
    sb = (sb + 1023) & ~1023u;

    const int tid  = threadIdx.x;
    const int lane = tid & 31, wq = tid >> 5;
    const int l15 = lane & 15, lh = lane >> 4;
    const int g4 = lane >> 2, t4 = lane & 3;
    const int b = blockIdx.z, h = blockIdx.y;
    const int q0 = blockIdx.x * 128;
    const size_t hoff = (size_t)h * HDIM;

    // ---- Q tile: 128 rows x 64 cols fp16 = 16KB ----
    {
        int qrow = tid >> 1;
        int cb = (tid & 1) * 4;
        size_t gidx = ((size_t)(b * SEQ + q0 + qrow)) * DMODEL + hoff;
        uint32_t st = sb + qrow * 128;
        #pragma unroll
        for (int c = 0; c < 4; c++) {
            uint32_t ph = (uint32_t)(((cb + c) ^ (qrow & 7)) << 4);
            CP16(st + ph, Qh + gidx + (cb + c) * 8);
        }
    }
    CP_COMMIT();

    const int krow = tid >> 2;
    const int kc0  = (tid & 3) * 2;
    auto load_kv = [&](int s, int kt) {
        uint32_t base = sb + 16384 + s * AKVSTAGE;
        size_t gidx = ((size_t)(b * SEQ + kt * 64 + krow)) * DMODEL + hoff;
        #pragma unroll
        for (int cc = 0; cc < 2; cc++) {
            int c = kc0 + cc;
            uint32_t off = krow * 128 + ((c ^ (krow & 7)) << 4);
            CP16(base + off,        Kh + gidx + c * 8);
            CP16(base + 8192 + off, Vh + gidx + c * 8);
        }
    };
    load_kv(0, 0);
    CP_COMMIT();

    float m0 = -1e30f, m1 = -1e30f, l0 = 0.f, l1 = 0.f;
    float o[8][4];
    #pragma unroll
    for (int j = 0; j < 8; j++)
        #pragma unroll
        for (int q = 0; q < 4; q++) o[j][q] = 0.f;

    const int NT = SEQ / 64;
    for (int kt = 0; kt < NT; kt++) {
        CP_WAIT0();
        __syncthreads();
        if (kt + 1 < NT) {
            load_kv((kt + 1) & 1, kt + 1);
            CP_COMMIT();
        }

        uint32_t stb = sb + 16384 + (kt & 1) * AKVSTAGE;

        float s[8][4];
        #pragma unroll
        for (int j = 0; j < 8; j++)
            #pragma unroll
            for (int q = 0; q < 4; q++) s[j][q] = 0.f;

        // ---- S = Q_scaled @ K^T (single fp16 term) ----
        #pragma unroll
        for (int kc = 0; kc < 4; kc++) {
            const int chunk = kc * 2 + lh;
            int arow = wq * 16 + l15;
            uint32_t aaddr = sb + arow * 128 + ((chunk ^ (arow & 7)) << 4);
            uint32_t qh_[4];
            ldsm4(aaddr, qh_[0], qh_[1], qh_[2], qh_[3]);
            #pragma unroll
            for (int g = 0; g < 4; g++) {
                int brow = g * 16 + l15;
                uint32_t baddr = stb + brow * 128 + ((chunk ^ (brow & 7)) << 4);
                uint32_t kh_[4];
                ldsm4(baddr, kh_[0], kh_[1], kh_[2], kh_[3]);
                mma16816h(s[2*g],   qh_, kh_[0], kh_[2]);
                mma16816h(s[2*g+1], qh_, kh_[1], kh_[3]);
            }
        }

        float mx0 = -1e30f, mx1 = -1e30f;
        #pragma unroll
        for (int j = 0; j < 8; j++) {
            mx0 = fmaxf(mx0, fmaxf(s[j][0], s[j][1]));
            mx1 = fmaxf(mx1, fmaxf(s[j][2], s[j][3]));
        }
        mx0 = fmaxf(mx0, __shfl_xor_sync(0xffffffffu, mx0, 1));
        mx0 = fmaxf(mx0, __shfl_xor_sync(0xffffffffu, mx0, 2));
        mx1 = fmaxf(mx1, __shfl_xor_sync(0xffffffffu, mx1, 1));
        mx1 = fmaxf(mx1, __shfl_xor_sync(0xffffffffu, mx1, 2));

        float mn0 = fmaxf(m0, mx0), mn1 = fmaxf(m1, mx1);
        float a0 = fexp2(m0 - mn0), a1 = fexp2(m1 - mn1);
        m0 = mn0; m1 = mn1;

        float sum0 = 0.f, sum1 = 0.f;
        #pragma unroll
        for (int j = 0; j < 8; j++) {
            s[j][0] = fexp2(s[j][0] - mn0);
            s[j][1] = fexp2(s[j][1] - mn0);
            s[j][2] = fexp2(s[j][2] - mn1);
            s[j][3] = fexp2(s[j][3] - mn1);
            sum0 += s[j][0] + s[j][1];
            sum1 += s[j][2] + s[j][3];
        }
        sum0 += __shfl_xor_sync(0xffffffffu, sum0, 1);
        sum0 += __shfl_xor_sync(0xffffffffu, sum0, 2);
        sum1 += __shfl_xor_sync(0xffffffffu, sum1, 1);
        sum1 += __shfl_xor_sync(0xffffffffu, sum1, 2);
        l0 = l0 * a0 + sum0;
        l1 = l1 * a1 + sum1;

        #pragma unroll
        for (int j = 0; j < 8; j++) {
            o[j][0] *= a0; o[j][1] *= a0;
            o[j][2] *= a1; o[j][3] *= a1;
        }

        // ---- O += P @ V (single fp16 term) ----
        #pragma unroll
        for (int kc = 0; kc < 4; kc++) {
            uint32_t ph_[4];
            ph_[0] = pack_h2(s[2*kc][0],   s[2*kc][1]);
            ph_[1] = pack_h2(s[2*kc][2],   s[2*kc][3]);
            ph_[2] = pack_h2(s[2*kc+1][0], s[2*kc+1][1]);
            ph_[3] = pack_h2(s[2*kc+1][2], s[2*kc+1][3]);

            int vrow = kc * 16 + (lane & 7) + ((lane >> 3) & 1) * 8;
            #pragma unroll
            for (int nn = 0; nn < 4; nn++) {
                int colchunk = nn * 2 + (lane >> 4);
                uint32_t vaddr = stb + 8192 + vrow * 128
                               + ((colchunk ^ (vrow & 7)) << 4);
                uint32_t vh_[4];
                ldsm4t(vaddr, vh_[0], vh_[1], vh_[2], vh_[3]);
                mma16816h(o[2*nn],   ph_, vh_[0], vh_[1]);
                mma16816h(o[2*nn+1], ph_, vh_[2], vh_[3]);
            }
        }
    }

    float i0 = 1.0f / l0, i1 = 1.0f / l1;
    int row0 = b * SEQ + q0 + wq * 16 + g4;
    #pragma unroll
    for (int j = 0; j < 8; j++) {
        int col = (int)hoff + j * 8 + t4 * 2;
        uint32_t h0, lo0, h1, lo1;
        split2(o[j][0] * i0, o[j][1] * i0, h0, lo0);
        split2(o[j][2] * i1, o[j][3] * i1, h1, lo1);
        *(uint32_t*)(Oh + (size_t)row0 * DMODEL + col)       = h0;
        *(uint32_t*)(Ol + (size_t)row0 * DMODEL + col)       = lo0;
        *(uint32_t*)(Oh + (size_t)(row0 + 8) * DMODEL + col) = h1;
        *(uint32_t*)(Ol + (size_t)(row0 + 8) * DMODEL + col) = lo1;
    }
}

// ---------------------------------------------------------------------------
// Fused residual add + LayerNorm over (y0 + y1 + y2 + residual).
// ---------------------------------------------------------------------------
__global__ void __launch_bounds__(256) ln_res_kernel(
    const float* __restrict__ y0, const float* __restrict__ y1,
    const float* __restrict__ y2, const float* __restrict__ r,
    const float* __restrict__ g, const float* __restrict__ b,
    float* __restrict__ o, bf16* __restrict__ oh, bf16* __restrict__ ol)
{
    const int row = blockIdx.x;
    const int tid = threadIdx.x;
    const float* y0p = y0 + (size_t)row * DMODEL;
    const float* y1p = y1 + (size_t)row * DMODEL;
    const float* y2p = y2 + (size_t)row * DMODEL;
    const float* rp  = r  + (size_t)row * DMODEL;

    float v[3];
    float s = 0.f, ss = 0.f;
    #pragma unroll
    for (int j = 0; j < 3; j++) {
        int c = tid + j * 256;
        float a = y0p[c] + y1p[c] + y2p[c] + rp[c];
        v[j] = a; s += a; ss += a * a;
    }
    #pragma unroll
    for (int off = 16; off; off >>= 1) {
        s  += __shfl_xor_sync(0xffffffffu, s, off);
        ss += __shfl_xor_sync(0xffffffffu, ss, off);
    }
    __shared__ float sred[16];
    if ((tid & 31) == 0) { sred[tid >> 5] = s; sred[8 + (tid >> 5)] = ss; }
    __syncthreads();
    if (tid == 0) {
        float S = 0.f, SS = 0.f;
        #pragma unroll
        for (int w = 0; w < 8; w++) { S += sred[w]; SS += sred[8 + w]; }
        sred[0] = S * (1.0f / DMODEL);
        sred[1] = SS * (1.0f / DMODEL);
    }
    __syncthreads();
    float mu  = sred[0];
    float var = sred[1] - mu * mu;
    float rstd = rsqrtf(var + 1e-5f);
    float* op = o + (size_t)row * DMODEL;
    #pragma unroll
    for (int j = 0; j < 3; j++) {
        int c = tid + j * 256;
        float val = (v[j] - mu) * rstd * g[c] + b[c];
        op[c] = val;
        if (oh) {
            bf16 hv = __float2bfloat16(val);
            oh[(size_t)row * DMODEL + c] = hv;
            ol[(size_t)row * DMODEL + c] =
                __float2bfloat16(val - __bfloat162float(hv));
        }
    }
}

// ---------------------------------------------------------------------------
extern "C" void kernel_launch(void* const* d_in, const int* in_sizes, int n_in,
                              void* d_out, int out_size)
{
    const float* x     = (const float*)d_in[0];
    const float* Wq    = (const float*)d_in[1];
    const float* bq    = (const float*)d_in[2];
    const float* Wk    = (const float*)d_in[3];
    const float* bk    = (const float*)d_in[4];
    const float* Wv    = (const float*)d_in[5];
    const float* bv    = (const float*)d_in[6];
    const float* Wo    = (const float*)d_in[7];
    const float* bo    = (const float*)d_in[8];
    const float* ln1g  = (const float*)d_in[9];
    const float* ln1b  = (const float*)d_in[10];
    const float* ln2g  = (const float*)d_in[11];
    const float* ln2b  = (const float*)d_in[12];
    const float* W1    = (const float*)d_in[13];
    const float* b1    = (const float*)d_in[14];
    const float* W2    = (const float*)d_in[15];
    const float* b2    = (const float*)d_in[16];
    float* out = (float*)d_out;

    float *p, *p2, *p3, *x1, *f, *f2, *f3;
    cudaGetSymbolAddress((void**)&p,  g_p);
    cudaGetSymbolAddress((void**)&p2, g_p2);
    cudaGetSymbolAddress((void**)&p3, g_p3);
    cudaGetSymbolAddress((void**)&x1, g_x1);
    cudaGetSymbolAddress((void**)&f,  g_f);
    cudaGetSymbolAddress((void**)&f2, g_f2);
    cudaGetSymbolAddress((void**)&f3, g_f3);

    bf16 *xh,*xl,*qh,*kh,*vh,*ah,*al,*x1h,*x1l,*hh,*hl;
    bf16 *Wqh,*Wql,*Wkh,*Wkl,*Wvh,*Wvl,*Woh,*Wol,*W1h,*W1l,*W2h,*W2l;
    cudaGetSymbolAddress((void**)&xh,  g_xh);  cudaGetSymbolAddress((void**)&xl,  g_xl);
    cudaGetSymbolAddress((void**)&qh,  g_qh);
    cudaGetSymbolAddress((void**)&kh,  g_kh);
    cudaGetSymbolAddress((void**)&vh,  g_vh);
    cudaGetSymbolAddress((void**)&ah,  g_ah);  cudaGetSymbolAddress((void**)&al,  g_al);
    cudaGetSymbolAddress((void**)&x1h, g_x1h); cudaGetSymbolAddress((void**)&x1l, g_x1l);
    cudaGetSymbolAddress((void**)&hh,  g_hh);  cudaGetSymbolAddress((void**)&hl,  g_hl);
    cudaGetSymbolAddress((void**)&Wqh, g_Wqh); cudaGetSymbolAddress((void**)&Wql, g_Wql);
    cudaGetSymbolAddress((void**)&Wkh, g_Wkh); cudaGetSymbolAddress((void**)&Wkl, g_Wkl);
    cudaGetSymbolAddress((void**)&Wvh, g_Wvh); cudaGetSymbolAddress((void**)&Wvl, g_Wvl);
    cudaGetSymbolAddress((void**)&Woh, g_Woh); cudaGetSymbolAddress((void**)&Wol, g_Wol);
    cudaGetSymbolAddress((void**)&W1h, g_W1h); cudaGetSymbolAddress((void**)&W1l, g_W1l);
    cudaGetSymbolAddress((void**)&W2h, g_W2h); cudaGetSymbolAddress((void**)&W2l, g_W2l);

    cudaFuncSetAttribute(gemm_mma<2>,
                         cudaFuncAttributeMaxDynamicSharedMemorySize, GSMEM_BYTES);
    cudaFuncSetAttribute(gemm_splitk,
                         cudaFuncAttributeMaxDynamicSharedMemorySize, GSMEM_BYTES);
    cudaFuncSetAttribute(gemm_qkv,
                         cudaFuncAttributeMaxDynamicSharedMemorySize, GSMEM_BYTES);
    cudaFuncSetAttribute(attn_mma,
                         cudaFuncAttributeMaxDynamicSharedMemorySize, ASMEM_BYTES);

    dim3 blk(256);

    // Merged split conversion, MLP=4
    cvt_all_kernel<<<CB_TOTAL, blk>>>(x, Wq, Wk, Wv, Wo, W1, W2,
                                      xh, xl, Wqh, Wql, Wkh, Wkl, Wvh, Wvl,
                                      Woh, Wol, W1h, W1l, W2h, W2l);

    // QKV combined (all single fp16 out; Q pre-scaled)
    dim3 gqkv(DMODEL / 128, NTOK / 128, 3);
    gemm_qkv<<<gqkv, blk, GSMEM_BYTES>>>(xh, xl, Wqh, Wql, Wkh, Wkl, Wvh, Wvl,
                                         bq, bk, bv, qh, kh, vh);

    // Attention (exp2-domain; all-fp16 single-term S and P@V)
    dim3 ga(SEQ / 128, NHEAD, BATCH);
    attn_mma<<<ga, blk, ASMEM_BYTES>>>(qh, kh, vh, ah, al);

    // Output projection (split-K x3) + residual LN1
    dim3 gS(DMODEL / 128, NTOK / 128, 3);
    gemm_splitk<<<gS, blk, GSMEM_BYTES>>>(ah, al, Woh, Wol, bo, p, p2, p3,
                                          DMODEL, DMODEL);
    ln_res_kernel<<<NTOK, blk>>>(p, p2, p3, x, ln1g, ln1b, x1, x1h, x1l);

    // FFN1 (GELU, bf16 split hidden)
    dim3 gF(FFND / 128, NTOK / 128);
    gemm_mma<2><<<gF, blk, GSMEM_BYTES>>>(x1h, x1l, W1h, W1l, b1,
                                          nullptr, hh, hl, FFND, DMODEL);
    // FFN2 (split-K x3) + residual LN2 -> out
    gemm_splitk<<<gS, blk, GSMEM_BYTES>>>(hh, hl, W2h, W2l, b2, f, f2, f3,
                                          DMODEL, FFND);
    ln_res_kernel<<<NTOK, blk>>>(f, f2, f3, x1, ln2g, ln2b, out, nullptr, nullptr);
}